// round 12
// baseline (speedup 1.0000x reference)
#include <cuda_runtime.h>
#include <cuda_fp16.h>
#include <stdint.h>
#include <math.h>

#define BB   16
#define LSEQ 1024
#define DDIM 512
typedef __half h16;

#define NQ   8388608    // B*L*D
#define NATT 16777216   // B*L*L
#define NW   262144     // D*D
#define WSC  32.0f      // W pre-scale (keeps W-lo out of fp16 subnormals)
#define WINV 0.03125f

// ---------------- scratch (device globals; no allocation allowed) ----------
__device__ __align__(16) h16 g_qh[NQ],    g_ql[NQ];
__device__ __align__(16) h16 g_kh[NQ],    g_kl[NQ];
__device__ __align__(16) h16 g_vh[NQ];                     // v: hi only (A-role, 2p)
__device__ __align__(16) h16 g_disth[NATT], g_distl[NATT];
__device__ __align__(16) h16 g_Wh[6][NW], g_Wl[6][NW];     // 32*W split
__device__ __align__(16) h16 g_qph[NQ];                    // hi only (A in attn 2p)
__device__ __align__(16) h16 g_kph[NQ],   g_kpl[NQ];       // B in attn op0
__device__ __align__(16) h16 g_vpTh[NQ],  g_vpTl[NQ];      // [b][d][m], B in av
__device__ __align__(16) h16 g_qt0Th[NQ], g_qt0Tl[NQ];     // [b][d][m], B in bmm
__device__ __align__(16) h16 g_kt0Th[NQ], g_kt0Tl[NQ];
__device__ __align__(16) h16 g_qth[NQ],   g_qtl[NQ];       // A in attn op1 (3p)
__device__ __align__(16) h16 g_kth[NQ],   g_ktl[NQ];       // B in attn op1
__device__ __align__(16) h16 g_ath[NATT];                  // hi only (A in av 2p)
__device__ __align__(16) h16 g_o0h[NQ];                    // hi only (A in fc 2p)
__device__ float g_fc[NQ];

// ---------------- helpers ---------------------------------------------------
__device__ __forceinline__ uint32_t smem_u32(const void* p) {
    return (uint32_t)__cvta_generic_to_shared(p);
}
__device__ __forceinline__ uint32_t pack_h2(float a, float b) {
    __half2 t = __floats2half2_rn(a, b);
    return *reinterpret_cast<uint32_t*>(&t);
}
__device__ __forceinline__ void split1h(float v, float& h, float& l) {
    h = __half2float(__float2half_rn(v));
    l = v - h;
}
__device__ __forceinline__ float tanh_fast(float x) {
    float y;
    asm("tanh.approx.f32 %0, %1;" : "=f"(y) : "f"(x));
    return y;
}

// Big (3p-capable) layout: Ah(16K) Al(16K) Bh(16K) Bl(16K) = 64KB x 2 stages
#define BUF_SZ       65536
#define SMEM_BIG     (2 * BUF_SZ)
// Compact (2p) layout: Ah(16K) Bh(16K) Bl(16K) = 48KB x 2 stages
#define CBUF_SZ      49152
#define SMEM_COMPACT (2 * CBUF_SZ)

__device__ __forceinline__ uint32_t swz(uint32_t base, int row, int cb) {
    uint32_t off = ((uint32_t)row << 7) + (uint32_t)cb;
    return base + (off ^ ((off >> 3) & 0x70));
}
__device__ __forceinline__ uint32_t a_addr(uint32_t base, int row0, int kb, int lane) {
    int mat = lane >> 3;
    return swz(base, row0 + (lane & 7) + ((mat & 1) << 3), kb + ((mat >> 1) << 4));
}
__device__ __forceinline__ uint32_t b_addr(uint32_t base, int n0, int kb, int lane) {
    int mat = lane >> 3;
    return swz(base, n0 + (lane & 7) + ((mat >> 1) << 3), kb + ((mat & 1) << 4));
}
__device__ __forceinline__ void ldsm4(uint32_t a, uint32_t* r) {
    asm volatile("ldmatrix.sync.aligned.m8n8.x4.shared.b16 {%0,%1,%2,%3}, [%4];"
                 : "=r"(r[0]), "=r"(r[1]), "=r"(r[2]), "=r"(r[3]) : "r"(a));
}
// f32-accumulate MMA (main hi*hi product)
__device__ __forceinline__ void mma16816(float* d, const uint32_t* a, const uint32_t* b) {
    asm volatile(
        "mma.sync.aligned.m16n8k16.row.col.f32.f16.f16.f32 "
        "{%0,%1,%2,%3}, {%4,%5,%6,%7}, {%8,%9}, {%0,%1,%2,%3};"
        : "+f"(d[0]), "+f"(d[1]), "+f"(d[2]), "+f"(d[3])
        : "r"(a[0]), "r"(a[1]), "r"(a[2]), "r"(a[3]), "r"(b[0]), "r"(b[1]));
}
// f16-accumulate MMA (lo correction products; sums are ~2^-11 of main term)
__device__ __forceinline__ void mma16816h(uint32_t* d, const uint32_t* a, const uint32_t* b) {
    asm volatile(
        "mma.sync.aligned.m16n8k16.row.col.f16.f16.f16.f16 "
        "{%0,%1}, {%2,%3,%4,%5}, {%6,%7}, {%0,%1};"
        : "+r"(d[0]), "+r"(d[1])
        : "r"(a[0]), "r"(a[1]), "r"(a[2]), "r"(a[3]), "r"(b[0]), "r"(b[1]));
}

// merge f16 accumulator into f32 accumulator (same fragment geometry)
__device__ __forceinline__ void merge_acc(float accF[4][4][4], const uint32_t accH[4][4][2]) {
#pragma unroll
    for (int mi = 0; mi < 4; mi++)
#pragma unroll
        for (int ni = 0; ni < 4; ni++) {
            __half2 h0 = *reinterpret_cast<const __half2*>(&accH[mi][ni][0]);
            __half2 h1 = *reinterpret_cast<const __half2*>(&accH[mi][ni][1]);
            accF[mi][ni][0] += __low2float(h0);
            accF[mi][ni][1] += __high2float(h0);
            accF[mi][ni][2] += __low2float(h1);
            accF[mi][ni][3] += __high2float(h1);
        }
}

struct GOps { const h16 *Ah, *Al, *Bh, *Bl; int lda, ldb, p3; };

// async-copy one 128-row x 64-h16 (128B/row) tile into swizzled SMEM
__device__ __forceinline__ void load_tile_async(const h16* __restrict__ g, int ld,
                                                uint32_t sdst) {
    int t = threadIdx.x;
#pragma unroll
    for (int i = 0; i < 4; i++) {
        int u   = t + (i << 8);
        int row = u >> 3;
        int seg = (u & 7) << 4;
        const char* src = reinterpret_cast<const char*>(g + (long)row * ld) + seg;
        asm volatile("cp.async.cg.shared.global [%0], [%1], 16;"
                     :: "r"(swz(sdst, row, seg)), "l"(src));
    }
}

// ===== big (3p-layout) path: used by proj3p / bmm / attn =====
__device__ __forceinline__ void issue_chunk(const GOps& o, int k0, uint32_t buf) {
    load_tile_async(o.Ah + k0, o.lda, buf);
    if (o.p3) load_tile_async(o.Al + k0, o.lda, buf + 16384);
    load_tile_async(o.Bh + k0, o.ldb, buf + 32768);
    load_tile_async(o.Bl + k0, o.ldb, buf + 49152);
    asm volatile("cp.async.commit_group;");
}
__device__ __forceinline__ void compute_chunk(uint32_t buf, int lane, int wm, int wn,
                                              float accF[4][4][4], uint32_t accH[4][4][2],
                                              int p3) {
#pragma unroll
    for (int ks = 0; ks < 4; ks++) {
        const int kb = ks * 32;
        uint32_t aH[4][4], aL[4][4], bH[8], bL[8];
#pragma unroll
        for (int mi = 0; mi < 4; mi++) ldsm4(a_addr(buf, wm + mi * 16, kb, lane), aH[mi]);
        if (p3) {
#pragma unroll
            for (int mi = 0; mi < 4; mi++)
                ldsm4(a_addr(buf + 16384, wm + mi * 16, kb, lane), aL[mi]);
        }
        ldsm4(b_addr(buf + 32768, wn,      kb, lane), bH);
        ldsm4(b_addr(buf + 32768, wn + 16, kb, lane), bH + 4);
        ldsm4(b_addr(buf + 49152, wn,      kb, lane), bL);
        ldsm4(b_addr(buf + 49152, wn + 16, kb, lane), bL + 4);
#pragma unroll
        for (int mi = 0; mi < 4; mi++)
#pragma unroll
            for (int ni = 0; ni < 4; ni++) {
                mma16816 (accF[mi][ni], aH[mi], bH + ni * 2);
                mma16816h(accH[mi][ni], aH[mi], bL + ni * 2);
            }
        if (p3) {
#pragma unroll
            for (int mi = 0; mi < 4; mi++)
#pragma unroll
                for (int ni = 0; ni < 4; ni++)
                    mma16816h(accH[mi][ni], aL[mi], bH + ni * 2);
        }
    }
}
__device__ __forceinline__ void run_gemm(const GOps* ops, int nops, int cpo,
                                         uint32_t sb, float accF[4][4][4],
                                         uint32_t accH[4][4][2]) {
    const int lane = threadIdx.x & 31, wid = threadIdx.x >> 5;
    const int wm = (wid >> 2) * 64, wn = (wid & 3) * 32;
    const int C = nops * cpo;

    issue_chunk(ops[0], 0, sb);
    for (int c = 0; c < C; c++) {
        if (c + 1 < C) {
            const GOps& o = ops[(c + 1) / cpo];
            issue_chunk(o, ((c + 1) % cpo) * 64, sb + ((c + 1) & 1) * BUF_SZ);
            asm volatile("cp.async.wait_group 1;" ::: "memory");
        } else {
            asm volatile("cp.async.wait_group 0;" ::: "memory");
        }
        __syncthreads();
        compute_chunk(sb + (c & 1) * BUF_SZ, lane, wm, wn, accF, accH, ops[c / cpo].p3);
        __syncthreads();
    }
}

// ===== compact (2p-layout) path: Ah / Bh(+16K) / Bl(+32K), 48KB stages =====
__device__ __forceinline__ void issue_chunk_c(const GOps& o, int k0, uint32_t buf) {
    load_tile_async(o.Ah + k0, o.lda, buf);
    load_tile_async(o.Bh + k0, o.ldb, buf + 16384);
    load_tile_async(o.Bl + k0, o.ldb, buf + 32768);
    asm volatile("cp.async.commit_group;");
}
__device__ __forceinline__ void compute_chunk_c(uint32_t buf, int lane, int wm, int wn,
                                                float accF[4][4][4], uint32_t accH[4][4][2]) {
#pragma unroll
    for (int ks = 0; ks < 4; ks++) {
        const int kb = ks * 32;
        uint32_t aH[4][4], bH[8], bL[8];
#pragma unroll
        for (int mi = 0; mi < 4; mi++) ldsm4(a_addr(buf, wm + mi * 16, kb, lane), aH[mi]);
        ldsm4(b_addr(buf + 16384, wn,      kb, lane), bH);
        ldsm4(b_addr(buf + 16384, wn + 16, kb, lane), bH + 4);
        ldsm4(b_addr(buf + 32768, wn,      kb, lane), bL);
        ldsm4(b_addr(buf + 32768, wn + 16, kb, lane), bL + 4);
#pragma unroll
        for (int mi = 0; mi < 4; mi++)
#pragma unroll
            for (int ni = 0; ni < 4; ni++) {
                mma16816 (accF[mi][ni], aH[mi], bH + ni * 2);
                mma16816h(accH[mi][ni], aH[mi], bL + ni * 2);
            }
    }
}
__device__ __forceinline__ void run_gemm_c(const GOps& op, int cpo,
                                           uint32_t sb, float accF[4][4][4],
                                           uint32_t accH[4][4][2]) {
    const int lane = threadIdx.x & 31, wid = threadIdx.x >> 5;
    const int wm = (wid >> 2) * 64, wn = (wid & 3) * 32;

    issue_chunk_c(op, 0, sb);
    for (int c = 0; c < cpo; c++) {
        if (c + 1 < cpo) {
            issue_chunk_c(op, (c + 1) * 64, sb + ((c + 1) & 1) * CBUF_SZ);
            asm volatile("cp.async.wait_group 1;" ::: "memory");
        } else {
            asm volatile("cp.async.wait_group 0;" ::: "memory");
        }
        __syncthreads();
        compute_chunk_c(sb + (c & 1) * CBUF_SZ, lane, wm, wn, accF, accH);
        __syncthreads();
    }
}

// epilogue helpers
__device__ __forceinline__ void epi_hl(h16* Dh, h16* Dl, long m0, int n0, int ld,
                                       const float acc[4][4][4], float sc) {
    const int lane = threadIdx.x & 31, wid = threadIdx.x >> 5;
    const int wm = (wid >> 2) * 64, wn = (wid & 3) * 32;
    const int gr = lane >> 2, cp = (lane & 3) * 2;
#pragma unroll
    for (int mi = 0; mi < 4; mi++)
#pragma unroll
        for (int ni = 0; ni < 4; ni++)
#pragma unroll
            for (int h = 0; h < 2; h++) {
                int r = wm + mi * 16 + gr + h * 8;
                int c = wn + ni * 8 + cp;
                float h0, l0, h1, l1;
                split1h(acc[mi][ni][h * 2]     * sc, h0, l0);
                split1h(acc[mi][ni][h * 2 + 1] * sc, h1, l1);
                long base = (m0 + r) * (long)ld + n0 + c;
                *reinterpret_cast<uint32_t*>(Dh + base) = pack_h2(h0, h1);
                *reinterpret_cast<uint32_t*>(Dl + base) = pack_h2(l0, l1);
            }
}
__device__ __forceinline__ void epi_h(h16* Dh, long m0, int n0, int ld,
                                      const float acc[4][4][4], float sc) {
    const int lane = threadIdx.x & 31, wid = threadIdx.x >> 5;
    const int wm = (wid >> 2) * 64, wn = (wid & 3) * 32;
    const int gr = lane >> 2, cp = (lane & 3) * 2;
#pragma unroll
    for (int mi = 0; mi < 4; mi++)
#pragma unroll
        for (int ni = 0; ni < 4; ni++)
#pragma unroll
            for (int h = 0; h < 2; h++) {
                int r = wm + mi * 16 + gr + h * 8;
                int c = wn + ni * 8 + cp;
                long base = (m0 + r) * (long)ld + n0 + c;
                *reinterpret_cast<uint32_t*>(Dh + base) =
                    pack_h2(acc[mi][ni][h * 2] * sc, acc[mi][ni][h * 2 + 1] * sc);
            }
}

// ---------------------------------------------------------------------------
// proj2p: z = 0 qp, 1 kp, 2 vpT  (2-product, compact SMEM)
// ---------------------------------------------------------------------------
__global__ __launch_bounds__(256, 1)
void proj2p_tc(const int* __restrict__ lens) {
    extern __shared__ char smem[];
    uint32_t sb = smem_u32(smem);

    const int z = blockIdx.z;
    const long m0 = (long)blockIdx.y * 128;

    if (z == 1 || z == 2) {
        const int len = lens[(int)(m0 >> 10)];
        const int lm  = (int)(m0 & 1023);
        const int lim = (z == 1) ? ((len + 127) & ~127) : ((len + 63) & ~63);
        if (lm >= lim) return;
    }

    const int n0 = blockIdx.x * 128;
    GOps op;
    op.lda = DDIM; op.ldb = DDIM; op.Al = nullptr; op.p3 = 0;
    h16 *Dh, *Dl;
    switch (z) {
        case 0: op.Ah = g_qh; op.Bh = g_Wh[0]; op.Bl = g_Wl[0]; Dh = g_qph;  Dl = nullptr; break;
        case 1: op.Ah = g_kh; op.Bh = g_Wh[1]; op.Bl = g_Wl[1]; Dh = g_kph;  Dl = g_kpl;   break;
        default:op.Ah = g_vh; op.Bh = g_Wh[2]; op.Bl = g_Wl[2]; Dh = g_vpTh; Dl = g_vpTl;  break;
    }
    op.Ah += m0 * DDIM;
    op.Bh += (long)n0 * DDIM; op.Bl += (long)n0 * DDIM;

    float acc[4][4][4] = {};
    uint32_t accH[4][4][2] = {};
    run_gemm_c(op, 8, sb, acc, accH);
    merge_acc(acc, accH);

    if (z == 0) { epi_h(Dh, m0, n0, DDIM, acc, WINV); return; }
    if (z == 1) { epi_hl(Dh, Dl, m0, n0, DDIM, acc, WINV); return; }

    // z == 2: transposed store via SMEM staging (Sh/Sl = 2 x 34816 B <= 96KB)
    h16* Sh = reinterpret_cast<h16*>(smem);
    h16* Sl = reinterpret_cast<h16*>(smem + 34816);
    const int lane = threadIdx.x & 31, wid = threadIdx.x >> 5;
    const int wm = (wid >> 2) * 64, wn = (wid & 3) * 32;
    const int gr = lane >> 2, cp = (lane & 3) * 2;
#pragma unroll
    for (int mi = 0; mi < 4; mi++)
#pragma unroll
        for (int ni = 0; ni < 4; ni++)
#pragma unroll
            for (int h = 0; h < 2; h++) {
                int r = wm + mi * 16 + gr + h * 8;
                int c = wn + ni * 8 + cp;
                float h0, l0, h1, l1;
                split1h(acc[mi][ni][h * 2]     * WINV, h0, l0);
                split1h(acc[mi][ni][h * 2 + 1] * WINV, h1, l1);
                Sh[(c    ) * 136 + r] = __float2half_rn(h0);
                Sh[(c + 1) * 136 + r] = __float2half_rn(h1);
                Sl[(c    ) * 136 + r] = __float2half_rn(l0);
                Sl[(c + 1) * 136 + r] = __float2half_rn(l1);
            }
    __syncthreads();
    const int t = threadIdx.x;
    const int d = t >> 1, half = t & 1;
    const int bb = (int)(m0 >> 10), lpos0 = (int)(m0 & 1023);
    long base = ((long)bb * DDIM + n0 + d) * LSEQ + lpos0 + half * 64;
    const uint4* sh = reinterpret_cast<const uint4*>(Sh + d * 136 + half * 64);
    const uint4* sl = reinterpret_cast<const uint4*>(Sl + d * 136 + half * 64);
    uint4* dh = reinterpret_cast<uint4*>(Dh + base);
    uint4* dl = reinterpret_cast<uint4*>(Dl + base);
#pragma unroll
    for (int j = 0; j < 8; j++) { dh[j] = sh[j]; dl[j] = sl[j]; }
}

// ---------------------------------------------------------------------------
// proj3p: z = 3 qt0T, 4 kt0T  (3-product precision chain, big SMEM)
// ---------------------------------------------------------------------------
__global__ __launch_bounds__(256, 1)
void proj3p_tc(const int* __restrict__ lens) {
    extern __shared__ char smem[];
    uint32_t sb = smem_u32(smem);
    (void)lens;

    const int z = 3 + blockIdx.z;
    const long m0 = (long)blockIdx.y * 128;
    const int  n0 = blockIdx.x * 128;

    GOps op;
    op.lda = DDIM; op.ldb = DDIM; op.p3 = 1;
    h16 *Dh, *Dl;
    if (z == 3) { op.Ah = g_qh; op.Al = g_ql; op.Bh = g_Wh[3]; op.Bl = g_Wl[3];
                  Dh = g_qt0Th; Dl = g_qt0Tl; }
    else        { op.Ah = g_kh; op.Al = g_kl; op.Bh = g_Wh[4]; op.Bl = g_Wl[4];
                  Dh = g_kt0Th; Dl = g_kt0Tl; }
    op.Ah += m0 * DDIM; op.Al += m0 * DDIM;
    op.Bh += (long)n0 * DDIM; op.Bl += (long)n0 * DDIM;

    float acc[4][4][4] = {};
    uint32_t accH[4][4][2] = {};
    run_gemm(&op, 1, 8, sb, acc, accH);
    merge_acc(acc, accH);

    // transposed store via SMEM staging
    h16* Sh = reinterpret_cast<h16*>(smem);
    h16* Sl = reinterpret_cast<h16*>(smem + 34816);
    const int lane = threadIdx.x & 31, wid = threadIdx.x >> 5;
    const int wm = (wid >> 2) * 64, wn = (wid & 3) * 32;
    const int gr = lane >> 2, cp = (lane & 3) * 2;
#pragma unroll
    for (int mi = 0; mi < 4; mi++)
#pragma unroll
        for (int ni = 0; ni < 4; ni++)
#pragma unroll
            for (int h = 0; h < 2; h++) {
                int r = wm + mi * 16 + gr + h * 8;
                int c = wn + ni * 8 + cp;
                float h0, l0, h1, l1;
                split1h(acc[mi][ni][h * 2]     * WINV, h0, l0);
                split1h(acc[mi][ni][h * 2 + 1] * WINV, h1, l1);
                Sh[(c    ) * 136 + r] = __float2half_rn(h0);
                Sh[(c + 1) * 136 + r] = __float2half_rn(h1);
                Sl[(c    ) * 136 + r] = __float2half_rn(l0);
                Sl[(c + 1) * 136 + r] = __float2half_rn(l1);
            }
    __syncthreads();
    const int t = threadIdx.x;
    const int d = t >> 1, half = t & 1;
    const int bb = (int)(m0 >> 10), lpos0 = (int)(m0 & 1023);
    long base = ((long)bb * DDIM + n0 + d) * LSEQ + lpos0 + half * 64;
    const uint4* sh = reinterpret_cast<const uint4*>(Sh + d * 136 + half * 64);
    const uint4* sl = reinterpret_cast<const uint4*>(Sl + d * 136 + half * 64);
    uint4* dh = reinterpret_cast<uint4*>(Dh + base);
    uint4* dl = reinterpret_cast<uint4*>(Dl + base);
#pragma unroll
    for (int j = 0; j < 8; j++) { dh[j] = sh[j]; dl[j] = sl[j]; }
}

// ---------------------------------------------------------------------------
// Stage B: qt/kt = dist @ qt0/kt0   (K = 1024, 3-product precision chain)
// ---------------------------------------------------------------------------
__global__ __launch_bounds__(256, 1)
void bmm_tc(const int* __restrict__ lens) {
    extern __shared__ char smem[];
    uint32_t sb = smem_u32(smem);

    const int z = blockIdx.z, b = z >> 1, isK = z & 1;
    const long m0 = (long)blockIdx.y * 128;
    if (isK) {
        const int len = lens[b];
        if ((int)m0 >= ((len + 127) & ~127)) return;
    }
    const h16* Bh = isK ? g_kt0Th : g_qt0Th;
    const h16* Bl = isK ? g_kt0Tl : g_qt0Tl;
    h16* Dh = isK ? g_kth : g_qth;
    h16* Dl = isK ? g_ktl : g_qtl;

    const int n0 = blockIdx.x * 128;

    GOps op;
    op.Ah = g_disth + (long)b * LSEQ * LSEQ + m0 * LSEQ;
    op.Al = g_distl + (long)b * LSEQ * LSEQ + m0 * LSEQ;
    op.lda = LSEQ; op.p3 = 1;
    op.Bh = Bh + (long)b * LSEQ * DDIM + (long)n0 * LSEQ;
    op.Bl = Bl + (long)b * LSEQ * DDIM + (long)n0 * LSEQ;
    op.ldb = LSEQ;
    float acc[4][4][4] = {};
    uint32_t accH[4][4][2] = {};
    run_gemm(&op, 1, 16, sb, acc, accH);
    merge_acc(acc, accH);

    epi_hl(Dh + (long)b * LSEQ * DDIM, Dl + (long)b * LSEQ * DDIM, m0, n0, DDIM, acc, 1.0f);
}

// ---------------------------------------------------------------------------
// attn zero-fill for fully-masked tiles (independent of all GEMMs)
// ---------------------------------------------------------------------------
__global__ __launch_bounds__(256)
void attn_zero(float* __restrict__ out_attn, const int* __restrict__ lens) {
    const int b = blockIdx.z;
    const long m0 = (long)blockIdx.y * 128;
    const int  n0 = blockIdx.x * 128;
    if (n0 < lens[b]) return;
    const long arow0 = (long)b * LSEQ * LSEQ;
    const int t = threadIdx.x;
    const int r = t >> 1, half = t & 1;
    float4* dst = reinterpret_cast<float4*>(
        out_attn + arow0 + (m0 + r) * (long)LSEQ + n0 + half * 64);
    const float4 z4 = make_float4(0.f, 0.f, 0.f, 0.f);
#pragma unroll
    for (int j = 0; j < 16; j++) dst[j] = z4;
}

// ---------------------------------------------------------------------------
// Stage C: attn = tanh(((qp.kp' + qt.kt')/sqrt(D)) * mask) * mask
// op0 (qp.kp): 2-product; op1 (qt.kt): 3-product. Masked tiles: early out.
// ---------------------------------------------------------------------------
__global__ __launch_bounds__(256, 1)
void attn_tc(float* __restrict__ out_attn, const int* __restrict__ lens) {
    extern __shared__ char smem[];
    uint32_t sb = smem_u32(smem);

    const int b = blockIdx.z;
    const long m0 = (long)blockIdx.y * 128;
    const int  n0 = blockIdx.x * 128;
    const int  len = lens[b];
    if (n0 >= len) return;   // zero-filled by attn_zero
    const long arow0 = (long)b * LSEQ * LSEQ;

    const long po = (long)b * LSEQ * DDIM;
    GOps ops[2];
    ops[0].Ah = g_qph + po + m0 * DDIM; ops[0].Al = nullptr; ops[0].p3 = 0;
    ops[0].Bh = g_kph + po + (long)n0 * DDIM; ops[0].Bl = g_kpl + po + (long)n0 * DDIM;
    ops[0].lda = DDIM; ops[0].ldb = DDIM;
    ops[1].Ah = g_qth + po + m0 * DDIM; ops[1].Al = g_qtl + po + m0 * DDIM; ops[1].p3 = 1;
    ops[1].Bh = g_kth + po + (long)n0 * DDIM; ops[1].Bl = g_ktl + po + (long)n0 * DDIM;
    ops[1].lda = DDIM; ops[1].ldb = DDIM;
    float acc[4][4][4] = {};
    uint32_t accH[4][4][2] = {};
    run_gemm(ops, 2, 8, sb, acc, accH);
    merge_acc(acc, accH);

    const float alpha = 0.044194173824159216f;   // 1/sqrt(512)
    const int lane = threadIdx.x & 31, wid = threadIdx.x >> 5;
    const int wm = (wid >> 2) * 64, wn = (wid & 3) * 32;
    const int gr = lane >> 2, cp = (lane & 3) * 2;

#pragma unroll
    for (int mi = 0; mi < 4; mi++)
#pragma unroll
        for (int ni = 0; ni < 4; ni++)
#pragma unroll
            for (int h = 0; h < 2; h++) {
                int r = wm + mi * 16 + gr + h * 8;
                int c = wn + ni * 8 + cp;
                int col = n0 + c;
                float t0 = (col     < len) ? tanh_fast(acc[mi][ni][h * 2]     * alpha) : 0.0f;
                float t1 = (col + 1 < len) ? tanh_fast(acc[mi][ni][h * 2 + 1] * alpha) : 0.0f;
                long base = arow0 + (m0 + r) * (long)LSEQ + col;
                *reinterpret_cast<float2*>(out_attn + base) = make_float2(t0, t1);
                *reinterpret_cast<uint32_t*>(g_ath + base) = pack_h2(t0, t1);
            }
}

// ---------------------------------------------------------------------------
// Stage D: out0 = attn @ vp   (2-product compact; only ceil(len/64) K-chunks)
// ---------------------------------------------------------------------------
__global__ __launch_bounds__(256, 1)
void av_tc(const int* __restrict__ lens) {
    extern __shared__ char smem[];
    uint32_t sb = smem_u32(smem);

    const int b = blockIdx.z;
    const long m0 = (long)blockIdx.y * 128;
    const int  n0 = blockIdx.x * 128;
    const int  len = lens[b];
    const int  cpo = (len + 63) >> 6;

    GOps op;
    op.Ah = g_ath + (long)b * LSEQ * LSEQ + m0 * LSEQ;
    op.Al = nullptr; op.p3 = 0;
    op.lda = LSEQ;
    op.Bh = g_vpTh + (long)b * LSEQ * DDIM + (long)n0 * LSEQ;
    op.Bl = g_vpTl + (long)b * LSEQ * DDIM + (long)n0 * LSEQ;
    op.ldb = LSEQ;
    float acc[4][4][4] = {};
    uint32_t accH[4][4][2] = {};
    run_gemm_c(op, cpo, sb, acc, accH);
    merge_acc(acc, accH);

    epi_h(g_o0h + (long)b * LSEQ * DDIM, m0, n0, DDIM, acc, 1.0f);
}

// ---------------------------------------------------------------------------
// Stage E: fc = out0 @ Wfc' + residual(q)  (2-product compact)
// ---------------------------------------------------------------------------
__global__ __launch_bounds__(256, 1)
void fc_tc(const float* __restrict__ q) {
    extern __shared__ char smem[];
    uint32_t sb = smem_u32(smem);

    const long m0 = (long)blockIdx.y * 128;
    const int  n0 = blockIdx.x * 128;

    GOps op;
    op.Ah = g_o0h + m0 * DDIM; op.Al = nullptr; op.p3 = 0; op.lda = DDIM;
    op.Bh = g_Wh[5] + (long)n0 * DDIM; op.Bl = g_Wl[5] + (long)n0 * DDIM; op.ldb = DDIM;
    float acc[4][4][4] = {};
    uint32_t accH[4][4][2] = {};
    run_gemm_c(op, 8, sb, acc, accH);
    merge_acc(acc, accH);

    const int lane = threadIdx.x & 31, wid = threadIdx.x >> 5;
    const int wm = (wid >> 2) * 64, wn = (wid & 3) * 32;
    const int gr = lane >> 2, cp = (lane & 3) * 2;
#pragma unroll
    for (int mi = 0; mi < 4; mi++)
#pragma unroll
        for (int ni = 0; ni < 4; ni++)
#pragma unroll
            for (int h = 0; h < 2; h++) {
                int r = wm + mi * 16 + gr + h * 8;
                int c = wn + ni * 8 + cp;
                long base = (m0 + r) * (long)DDIM + n0 + c;
                float2 rv = *reinterpret_cast<const float2*>(q + base);
                *reinterpret_cast<float2*>(g_fc + base) =
                    make_float2(acc[mi][ni][h * 2] * WINV + rv.x,
                                acc[mi][ni][h * 2 + 1] * WINV + rv.y);
            }
}

// ---------------------------------------------------------------------------
// fp32 -> fp16 hi/lo splits
// ---------------------------------------------------------------------------
__global__ __launch_bounds__(256)
void split_qkv(const float* __restrict__ q, const float* __restrict__ k,
               const float* __restrict__ v) {
    const int y = blockIdx.y;
    long i = (long)blockIdx.x * 256 + threadIdx.x;
    const float* s = (y == 0) ? q : (y == 1) ? k : v;
    float4 vv = reinterpret_cast<const float4*>(s)[i];
    float hx, lx, hy, ly, hz, lz, hw, lw;
    split1h(vv.x, hx, lx); split1h(vv.y, hy, ly);
    split1h(vv.z, hz, lz); split1h(vv.w, hw, lw);
    uint2 hh = make_uint2(pack_h2(hx, hy), pack_h2(hz, hw));
    uint2 ll = make_uint2(pack_h2(lx, ly), pack_h2(lz, lw));
    if (y == 0)      { reinterpret_cast<uint2*>(g_qh)[i] = hh; reinterpret_cast<uint2*>(g_ql)[i] = ll; }
    else if (y == 1) { reinterpret_cast<uint2*>(g_kh)[i] = hh; reinterpret_cast<uint2*>(g_kl)[i] = ll; }
    else             { reinterpret_cast<uint2*>(g_vh)[i] = hh; }
}

__global__ __launch_bounds__(256)
void split_dist(const float* __restrict__ d) {
    long i = (long)blockIdx.x * 256 + threadIdx.x;
    float4 vv = reinterpret_cast<const float4*>(d)[i];
    float hx, lx, hy, ly, hz, lz, hw, lw;
    split1h(vv.x, hx, lx); split1h(vv.y, hy, ly);
    split1h(vv.z, hz, lz); split1h(vv.w, hw, lw);
    reinterpret_cast<uint2*>(g_disth)[i] = make_uint2(pack_h2(hx, hy), pack_h2(hz, hw));
    reinterpret_cast<uint2*>(g_distl)[i] = make_uint2(pack_h2(lx, ly), pack_h2(lz, lw));
}

__global__ __launch_bounds__(256)
void split_w(const float* __restrict__ w0, const float* __restrict__ w1,
             const float* __restrict__ w2, const float* __restrict__ w3,
             const float* __restrict__ w4, const float* __restrict__ w5) {
    const float* s; int wi = blockIdx.y;
    switch (wi) {
        case 0: s = w0; break; case 1: s = w1; break; case 2: s = w2; break;
        case 3: s = w3; break; case 4: s = w4; break; default: s = w5; break;
    }
    long i = (long)blockIdx.x * 256 + threadIdx.x;
    float4 vv = reinterpret_cast<const float4*>(s)[i];
    float hx, lx, hy, ly, hz, lz, hw, lw;
    split1h(vv.x * WSC, hx, lx); split1h(vv.y * WSC, hy, ly);
    split1h(vv.z * WSC, hz, lz); split1h(vv.w * WSC, hw, lw);
    reinterpret_cast<uint2*>(g_Wh[wi])[i] = make_uint2(pack_h2(hx, hy), pack_h2(hz, hw));
    reinterpret_cast<uint2*>(g_Wl[wi])[i] = make_uint2(pack_h2(lx, ly), pack_h2(lz, lw));
}

// ---------------------------------------------------------------------------
// LayerNorm over D=512
// ---------------------------------------------------------------------------
__global__ __launch_bounds__(128)
void ln_kernel(const float* __restrict__ gamma, const float* __restrict__ beta,
               float* __restrict__ out) {
    const long row = blockIdx.x;
    const int  t   = threadIdx.x;
    float4 v = reinterpret_cast<const float4*>(g_fc)[row * 128 + t];
    float s  = v.x + v.y + v.z + v.w;
    float s2 = v.x * v.x + v.y * v.y + v.z * v.z + v.w * v.w;
#pragma unroll
    for (int o = 16; o; o >>= 1) {
        s  += __shfl_xor_sync(0xffffffffu, s,  o);
        s2 += __shfl_xor_sync(0xffffffffu, s2, o);
    }
    __shared__ float ss[4], ss2[4];
    if ((t & 31) == 0) { ss[t >> 5] = s; ss2[t >> 5] = s2; }
    __syncthreads();
    s  = ss[0] + ss[1] + ss[2] + ss[3];
    s2 = ss2[0] + ss2[1] + ss2[2] + ss2[3];
    const float mu  = s * (1.0f / 512.0f);
    const float var = s2 * (1.0f / 512.0f) - mu * mu;
    const float inv = rsqrtf(var + 1e-6f);
    float4 g  = reinterpret_cast<const float4*>(gamma)[t];
    float4 be = reinterpret_cast<const float4*>(beta)[t];
    float4 o;
    o.x = (v.x - mu) * inv * g.x + be.x;
    o.y = (v.y - mu) * inv * g.y + be.y;
    o.z = (v.z - mu) * inv * g.z + be.z;
    o.w = (v.w - mu) * inv * g.w + be.w;
    reinterpret_cast<float4*>(out)[row * 128 + t] = o;
}

// ---------------------------------------------------------------------------
extern "C" void kernel_launch(void* const* d_in, const int* in_sizes, int n_in,
                              void* d_out, int out_size)
{
    (void)in_sizes; (void)n_in; (void)out_size;
    const float* q     = (const float*)d_in[0];
    const float* k     = (const float*)d_in[1];
    const float* v     = (const float*)d_in[2];
    const int*   lens  = (const int*)  d_in[3];
    const float* dist  = (const float*)d_in[4];
    const float* Wq    = (const float*)d_in[5];
    const float* Wk    = (const float*)d_in[6];
    const float* Wv    = (const float*)d_in[7];
    const float* Wqt   = (const float*)d_in[8];
    const float* Wkt   = (const float*)d_in[9];
    const float* Wfc   = (const float*)d_in[10];
    const float* gamma = (const float*)d_in[11];
    const float* beta  = (const float*)d_in[12];

    float* out_ln   = (float*)d_out;                       // [B, L, D]
    float* out_attn = out_ln + (size_t)BB * LSEQ * DDIM;   // [B, L, L]

    static cudaStream_t s1 = nullptr;
    static cudaEvent_t ev1 = nullptr, ev2 = nullptr;
    if (!s1) {
        cudaStreamCreateWithFlags(&s1, cudaStreamNonBlocking);
        cudaEventCreateWithFlags(&ev1, cudaEventDisableTiming);
        cudaEventCreateWithFlags(&ev2, cudaEventDisableTiming);
    }

    cudaFuncSetAttribute(proj2p_tc, cudaFuncAttributeMaxDynamicSharedMemorySize, SMEM_COMPACT);
    cudaFuncSetAttribute(proj3p_tc, cudaFuncAttributeMaxDynamicSharedMemorySize, SMEM_BIG);
    cudaFuncSetAttribute(bmm_tc,    cudaFuncAttributeMaxDynamicSharedMemorySize, SMEM_BIG);
    cudaFuncSetAttribute(attn_tc,   cudaFuncAttributeMaxDynamicSharedMemorySize, SMEM_BIG);
    cudaFuncSetAttribute(av_tc,     cudaFuncAttributeMaxDynamicSharedMemorySize, SMEM_COMPACT);
    cudaFuncSetAttribute(fc_tc,     cudaFuncAttributeMaxDynamicSharedMemorySize, SMEM_COMPACT);

    // main: input splits that everything downstream needs
    split_qkv <<<dim3(NQ / 4 / 256, 3), 256>>>(q, k, v);
    split_w   <<<dim3(NW / 4 / 256, 6), 256>>>(Wq, Wk, Wv, Wqt, Wkt, Wfc);

    // fork: cheap independent work on s1 (attn zero-fill + proj2p)
    cudaEventRecord(ev1, 0);
    cudaStreamWaitEvent(s1, ev1, 0);
    proj2p_tc<<<dim3(4, 128, 3), 256, SMEM_COMPACT, s1>>>(lens);
    attn_zero<<<dim3(8, 8, 16), 256, 0, s1>>>(out_attn, lens);
    cudaEventRecord(ev2, s1);

    // main: critical chain
    split_dist<<<NATT / 4 / 256, 256>>>(dist);
    proj3p_tc<<<dim3(4, 128, 2), 256, SMEM_BIG>>>(lens);
    bmm_tc   <<<dim3(4, 8, 32),  256, SMEM_BIG>>>(lens);

    // join, then serial tail
    cudaStreamWaitEvent(0, ev2, 0);
    attn_tc<<<dim3(8, 8, 16),  256, SMEM_BIG>>>(out_attn, lens);
    av_tc  <<<dim3(4, 8, 16),  256, SMEM_COMPACT>>>(lens);
    fc_tc  <<<dim3(4, 128, 1), 256, SMEM_COMPACT>>>(q);
    ln_kernel<<<BB * LSEQ, 128>>>(gamma, beta, out_ln);
}

// round 13
// speedup vs baseline: 1.1081x; 1.1081x over previous
#include <cuda_runtime.h>
#include <cuda_fp16.h>
#include <stdint.h>
#include <math.h>

#define BB   16
#define LSEQ 1024
#define DDIM 512
typedef __half h16;

#define NQ   8388608    // B*L*D
#define NATT 16777216   // B*L*L
#define NW   262144     // D*D
#define WSC  32.0f      // W pre-scale (keeps W-lo out of fp16 subnormals)
#define WINV 0.03125f

// ---------------- scratch (device globals; no allocation allowed) ----------
__device__ __align__(16) h16 g_qh[NQ],    g_ql[NQ];
__device__ __align__(16) h16 g_kh[NQ],    g_kl[NQ];
__device__ __align__(16) h16 g_vh[NQ];                     // v: hi only
__device__ __align__(16) h16 g_disth[NATT], g_distl[NATT];
__device__ __align__(16) h16 g_Wh[6][NW], g_Wl[6][NW];     // 32*W split
__device__ __align__(16) h16 g_qph[NQ];                    // hi only
__device__ __align__(16) h16 g_kph[NQ];                    // hi only (1p attn op0)
__device__ __align__(16) h16 g_vpTh[NQ];                   // [b][d][m], hi only (1p av)
__device__ __align__(16) h16 g_qt0Th[NQ], g_qt0Tl[NQ];     // [b][d][m], B in bmm
__device__ __align__(16) h16 g_kt0Th[NQ], g_kt0Tl[NQ];
__device__ __align__(16) h16 g_qth[NQ],   g_qtl[NQ];       // A in attn op1 (3p)
__device__ __align__(16) h16 g_kth[NQ],   g_ktl[NQ];       // B in attn op1
__device__ __align__(16) h16 g_ath[NATT];                  // hi only (A in av)
__device__ __align__(16) h16 g_o0h[NQ];                    // hi only (A in fc 2p)
__device__ float g_fc[NQ];

// ---------------- helpers ---------------------------------------------------
__device__ __forceinline__ uint32_t smem_u32(const void* p) {
    return (uint32_t)__cvta_generic_to_shared(p);
}
__device__ __forceinline__ uint32_t pack_h2(float a, float b) {
    __half2 t = __floats2half2_rn(a, b);
    return *reinterpret_cast<uint32_t*>(&t);
}
__device__ __forceinline__ void split1h(float v, float& h, float& l) {
    h = __half2float(__float2half_rn(v));
    l = v - h;
}
__device__ __forceinline__ float tanh_fast(float x) {
    float y;
    asm("tanh.approx.f32 %0, %1;" : "=f"(y) : "f"(x));
    return y;
}

// Big (up-to-3p) layout: Ah(16K) Al(16K) Bh(16K) Bl(16K) = 64KB x 2 stages
#define BUF_SZ       65536
#define SMEM_BIG     (2 * BUF_SZ)
// Compact (2p) layout: Ah(16K) Bh(16K) Bl(16K) = 48KB x 2 stages
#define CBUF_SZ      49152
#define SMEM_COMPACT (2 * CBUF_SZ)
// Minimal (1p) layout: Ah(16K) Bh(16K) = 32KB x 2 stages
#define MBUF_SZ      32768
#define SMEM_MIN     (2 * MBUF_SZ)

__device__ __forceinline__ uint32_t swz(uint32_t base, int row, int cb) {
    uint32_t off = ((uint32_t)row << 7) + (uint32_t)cb;
    return base + (off ^ ((off >> 3) & 0x70));
}
__device__ __forceinline__ uint32_t a_addr(uint32_t base, int row0, int kb, int lane) {
    int mat = lane >> 3;
    return swz(base, row0 + (lane & 7) + ((mat & 1) << 3), kb + ((mat >> 1) << 4));
}
__device__ __forceinline__ uint32_t b_addr(uint32_t base, int n0, int kb, int lane) {
    int mat = lane >> 3;
    return swz(base, n0 + (lane & 7) + ((mat >> 1) << 3), kb + ((mat & 1) << 4));
}
__device__ __forceinline__ void ldsm4(uint32_t a, uint32_t* r) {
    asm volatile("ldmatrix.sync.aligned.m8n8.x4.shared.b16 {%0,%1,%2,%3}, [%4];"
                 : "=r"(r[0]), "=r"(r[1]), "=r"(r[2]), "=r"(r[3]) : "r"(a));
}
__device__ __forceinline__ void mma16816(float* d, const uint32_t* a, const uint32_t* b) {
    asm volatile(
        "mma.sync.aligned.m16n8k16.row.col.f32.f16.f16.f32 "
        "{%0,%1,%2,%3}, {%4,%5,%6,%7}, {%8,%9}, {%0,%1,%2,%3};"
        : "+f"(d[0]), "+f"(d[1]), "+f"(d[2]), "+f"(d[3])
        : "r"(a[0]), "r"(a[1]), "r"(a[2]), "r"(a[3]), "r"(b[0]), "r"(b[1]));
}

// mode: 1 = Ah*Bh; 2 = Ah*(Bh+Bl); 3 = 2 + Al*Bh
struct GOps { const h16 *Ah, *Al, *Bh, *Bl; int lda, ldb, mode; };

// async-copy one 128-row x 64-h16 (128B/row) tile into swizzled SMEM
__device__ __forceinline__ void load_tile_async(const h16* __restrict__ g, int ld,
                                                uint32_t sdst) {
    int t = threadIdx.x;
#pragma unroll
    for (int i = 0; i < 4; i++) {
        int u   = t + (i << 8);
        int row = u >> 3;
        int seg = (u & 7) << 4;
        const char* src = reinterpret_cast<const char*>(g + (long)row * ld) + seg;
        asm volatile("cp.async.cg.shared.global [%0], [%1], 16;"
                     :: "r"(swz(sdst, row, seg)), "l"(src));
    }
}

// ===== big (up-to-3p) path: proj3p / bmm / attn =====
__device__ __forceinline__ void issue_chunk(const GOps& o, int k0, uint32_t buf) {
    load_tile_async(o.Ah + k0, o.lda, buf);
    if (o.mode == 3) load_tile_async(o.Al + k0, o.lda, buf + 16384);
    load_tile_async(o.Bh + k0, o.ldb, buf + 32768);
    if (o.mode >= 2) load_tile_async(o.Bl + k0, o.ldb, buf + 49152);
    asm volatile("cp.async.commit_group;");
}
__device__ __forceinline__ void compute_chunk(uint32_t buf, int lane, int wm, int wn,
                                              float acc[4][4][4], int mode) {
#pragma unroll
    for (int ks = 0; ks < 4; ks++) {
        const int kb = ks * 32;
        uint32_t aH[4][4], aL[4][4], bH[8], bL[8];
#pragma unroll
        for (int mi = 0; mi < 4; mi++) ldsm4(a_addr(buf, wm + mi * 16, kb, lane), aH[mi]);
        if (mode == 3) {
#pragma unroll
            for (int mi = 0; mi < 4; mi++)
                ldsm4(a_addr(buf + 16384, wm + mi * 16, kb, lane), aL[mi]);
        }
        ldsm4(b_addr(buf + 32768, wn,      kb, lane), bH);
        ldsm4(b_addr(buf + 32768, wn + 16, kb, lane), bH + 4);
        if (mode >= 2) {
            ldsm4(b_addr(buf + 49152, wn,      kb, lane), bL);
            ldsm4(b_addr(buf + 49152, wn + 16, kb, lane), bL + 4);
        }
#pragma unroll
        for (int mi = 0; mi < 4; mi++)
#pragma unroll
            for (int ni = 0; ni < 4; ni++)
                mma16816(acc[mi][ni], aH[mi], bH + ni * 2);
        if (mode >= 2) {
#pragma unroll
            for (int mi = 0; mi < 4; mi++)
#pragma unroll
                for (int ni = 0; ni < 4; ni++)
                    mma16816(acc[mi][ni], aH[mi], bL + ni * 2);
        }
        if (mode == 3) {
#pragma unroll
            for (int mi = 0; mi < 4; mi++)
#pragma unroll
                for (int ni = 0; ni < 4; ni++)
                    mma16816(acc[mi][ni], aL[mi], bH + ni * 2);
        }
    }
}
__device__ __forceinline__ void run_gemm(const GOps* ops, int nops, int cpo,
                                         uint32_t sb, float acc[4][4][4]) {
    const int lane = threadIdx.x & 31, wid = threadIdx.x >> 5;
    const int wm = (wid >> 2) * 64, wn = (wid & 3) * 32;
    const int C = nops * cpo;

    issue_chunk(ops[0], 0, sb);
    for (int c = 0; c < C; c++) {
        if (c + 1 < C) {
            const GOps& o = ops[(c + 1) / cpo];
            issue_chunk(o, ((c + 1) % cpo) * 64, sb + ((c + 1) & 1) * BUF_SZ);
            asm volatile("cp.async.wait_group 1;" ::: "memory");
        } else {
            asm volatile("cp.async.wait_group 0;" ::: "memory");
        }
        __syncthreads();
        compute_chunk(sb + (c & 1) * BUF_SZ, lane, wm, wn, acc, ops[c / cpo].mode);
        __syncthreads();
    }
}

// ===== compact (2p) path: Ah / Bh(+16K) / Bl(+32K), 48KB stages =====
__device__ __forceinline__ void issue_chunk_c(const GOps& o, int k0, uint32_t buf) {
    load_tile_async(o.Ah + k0, o.lda, buf);
    load_tile_async(o.Bh + k0, o.ldb, buf + 16384);
    load_tile_async(o.Bl + k0, o.ldb, buf + 32768);
    asm volatile("cp.async.commit_group;");
}
__device__ __forceinline__ void compute_chunk_c(uint32_t buf, int lane, int wm, int wn,
                                                float acc[4][4][4]) {
#pragma unroll
    for (int ks = 0; ks < 4; ks++) {
        const int kb = ks * 32;
        uint32_t aH[4][4], bH[8], bL[8];
#pragma unroll
        for (int mi = 0; mi < 4; mi++) ldsm4(a_addr(buf, wm + mi * 16, kb, lane), aH[mi]);
        ldsm4(b_addr(buf + 16384, wn,      kb, lane), bH);
        ldsm4(b_addr(buf + 16384, wn + 16, kb, lane), bH + 4);
        ldsm4(b_addr(buf + 32768, wn,      kb, lane), bL);
        ldsm4(b_addr(buf + 32768, wn + 16, kb, lane), bL + 4);
#pragma unroll
        for (int mi = 0; mi < 4; mi++)
#pragma unroll
            for (int ni = 0; ni < 4; ni++) {
                mma16816(acc[mi][ni], aH[mi], bH + ni * 2);
                mma16816(acc[mi][ni], aH[mi], bL + ni * 2);
            }
    }
}
__device__ __forceinline__ void run_gemm_c(const GOps& op, int cpo,
                                           uint32_t sb, float acc[4][4][4]) {
    const int lane = threadIdx.x & 31, wid = threadIdx.x >> 5;
    const int wm = (wid >> 2) * 64, wn = (wid & 3) * 32;

    issue_chunk_c(op, 0, sb);
    for (int c = 0; c < cpo; c++) {
        if (c + 1 < cpo) {
            issue_chunk_c(op, (c + 1) * 64, sb + ((c + 1) & 1) * CBUF_SZ);
            asm volatile("cp.async.wait_group 1;" ::: "memory");
        } else {
            asm volatile("cp.async.wait_group 0;" ::: "memory");
        }
        __syncthreads();
        compute_chunk_c(sb + (c & 1) * CBUF_SZ, lane, wm, wn, acc);
        __syncthreads();
    }
}

// ===== minimal (1p) path: Ah / Bh(+16K), 32KB stages (av) =====
__device__ __forceinline__ void issue_chunk_1(const GOps& o, int k0, uint32_t buf) {
    load_tile_async(o.Ah + k0, o.lda, buf);
    load_tile_async(o.Bh + k0, o.ldb, buf + 16384);
    asm volatile("cp.async.commit_group;");
}
__device__ __forceinline__ void compute_chunk_1(uint32_t buf, int lane, int wm, int wn,
                                                float acc[4][4][4]) {
#pragma unroll
    for (int ks = 0; ks < 4; ks++) {
        const int kb = ks * 32;
        uint32_t aH[4][4], bH[8];
#pragma unroll
        for (int mi = 0; mi < 4; mi++) ldsm4(a_addr(buf, wm + mi * 16, kb, lane), aH[mi]);
        ldsm4(b_addr(buf + 16384, wn,      kb, lane), bH);
        ldsm4(b_addr(buf + 16384, wn + 16, kb, lane), bH + 4);
#pragma unroll
        for (int mi = 0; mi < 4; mi++)
#pragma unroll
            for (int ni = 0; ni < 4; ni++)
                mma16816(acc[mi][ni], aH[mi], bH + ni * 2);
    }
}
__device__ __forceinline__ void run_gemm_1(const GOps& op, int cpo,
                                           uint32_t sb, float acc[4][4][4]) {
    const int lane = threadIdx.x & 31, wid = threadIdx.x >> 5;
    const int wm = (wid >> 2) * 64, wn = (wid & 3) * 32;

    issue_chunk_1(op, 0, sb);
    for (int c = 0; c < cpo; c++) {
        if (c + 1 < cpo) {
            issue_chunk_1(op, (c + 1) * 64, sb + ((c + 1) & 1) * MBUF_SZ);
            asm volatile("cp.async.wait_group 1;" ::: "memory");
        } else {
            asm volatile("cp.async.wait_group 0;" ::: "memory");
        }
        __syncthreads();
        compute_chunk_1(sb + (c & 1) * MBUF_SZ, lane, wm, wn, acc);
        __syncthreads();
    }
}

// epilogue helpers
__device__ __forceinline__ void epi_hl(h16* Dh, h16* Dl, long m0, int n0, int ld,
                                       const float acc[4][4][4], float sc) {
    const int lane = threadIdx.x & 31, wid = threadIdx.x >> 5;
    const int wm = (wid >> 2) * 64, wn = (wid & 3) * 32;
    const int gr = lane >> 2, cp = (lane & 3) * 2;
#pragma unroll
    for (int mi = 0; mi < 4; mi++)
#pragma unroll
        for (int ni = 0; ni < 4; ni++)
#pragma unroll
            for (int h = 0; h < 2; h++) {
                int r = wm + mi * 16 + gr + h * 8;
                int c = wn + ni * 8 + cp;
                float h0, l0, h1, l1;
                split1h(acc[mi][ni][h * 2]     * sc, h0, l0);
                split1h(acc[mi][ni][h * 2 + 1] * sc, h1, l1);
                long base = (m0 + r) * (long)ld + n0 + c;
                *reinterpret_cast<uint32_t*>(Dh + base) = pack_h2(h0, h1);
                *reinterpret_cast<uint32_t*>(Dl + base) = pack_h2(l0, l1);
            }
}
__device__ __forceinline__ void epi_h(h16* Dh, long m0, int n0, int ld,
                                      const float acc[4][4][4], float sc) {
    const int lane = threadIdx.x & 31, wid = threadIdx.x >> 5;
    const int wm = (wid >> 2) * 64, wn = (wid & 3) * 32;
    const int gr = lane >> 2, cp = (lane & 3) * 2;
#pragma unroll
    for (int mi = 0; mi < 4; mi++)
#pragma unroll
        for (int ni = 0; ni < 4; ni++)
#pragma unroll
            for (int h = 0; h < 2; h++) {
                int r = wm + mi * 16 + gr + h * 8;
                int c = wn + ni * 8 + cp;
                long base = (m0 + r) * (long)ld + n0 + c;
                *reinterpret_cast<uint32_t*>(Dh + base) =
                    pack_h2(acc[mi][ni][h * 2] * sc, acc[mi][ni][h * 2 + 1] * sc);
            }
}

// ---------------------------------------------------------------------------
// proj2p: z = 0 qp, 1 kp, 2 vpT  (2p compute; hi-only outputs)
// ---------------------------------------------------------------------------
__global__ __launch_bounds__(256, 2)
void proj2p_tc(const int* __restrict__ lens) {
    extern __shared__ char smem[];
    uint32_t sb = smem_u32(smem);

    const int z = blockIdx.z;
    const long m0 = (long)blockIdx.y * 128;

    if (z == 1 || z == 2) {
        const int len = lens[(int)(m0 >> 10)];
        const int lm  = (int)(m0 & 1023);
        const int lim = (z == 1) ? ((len + 127) & ~127) : ((len + 63) & ~63);
        if (lm >= lim) return;
    }

    const int n0 = blockIdx.x * 128;
    GOps op;
    op.lda = DDIM; op.ldb = DDIM; op.Al = nullptr; op.mode = 2;
    h16* Dh;
    switch (z) {
        case 0: op.Ah = g_qh; op.Bh = g_Wh[0]; op.Bl = g_Wl[0]; Dh = g_qph;  break;
        case 1: op.Ah = g_kh; op.Bh = g_Wh[1]; op.Bl = g_Wl[1]; Dh = g_kph;  break;
        default:op.Ah = g_vh; op.Bh = g_Wh[2]; op.Bl = g_Wl[2]; Dh = g_vpTh; break;
    }
    op.Ah += m0 * DDIM;
    op.Bh += (long)n0 * DDIM; op.Bl += (long)n0 * DDIM;

    float acc[4][4][4] = {};
    run_gemm_c(op, 8, sb, acc);

    if (z != 2) { epi_h(Dh, m0, n0, DDIM, acc, WINV); return; }

    // z == 2: transposed hi-only store via SMEM staging (34816 B)
    h16* Sh = reinterpret_cast<h16*>(smem);
    const int lane = threadIdx.x & 31, wid = threadIdx.x >> 5;
    const int wm = (wid >> 2) * 64, wn = (wid & 3) * 32;
    const int gr = lane >> 2, cp = (lane & 3) * 2;
    __syncthreads();
#pragma unroll
    for (int mi = 0; mi < 4; mi++)
#pragma unroll
        for (int ni = 0; ni < 4; ni++)
#pragma unroll
            for (int h = 0; h < 2; h++) {
                int r = wm + mi * 16 + gr + h * 8;
                int c = wn + ni * 8 + cp;
                Sh[(c    ) * 136 + r] = __float2half_rn(acc[mi][ni][h * 2]     * WINV);
                Sh[(c + 1) * 136 + r] = __float2half_rn(acc[mi][ni][h * 2 + 1] * WINV);
            }
    __syncthreads();
    const int t = threadIdx.x;
    const int d = t >> 1, half = t & 1;
    const int bb = (int)(m0 >> 10), lpos0 = (int)(m0 & 1023);
    long base = ((long)bb * DDIM + n0 + d) * LSEQ + lpos0 + half * 64;
    const uint4* sh = reinterpret_cast<const uint4*>(Sh + d * 136 + half * 64);
    uint4* dh = reinterpret_cast<uint4*>(Dh + base);
#pragma unroll
    for (int j = 0; j < 8; j++) dh[j] = sh[j];
}

// ---------------------------------------------------------------------------
// proj3p: z = 3 qt0T, 4 kt0T  (3-product precision chain, big SMEM)
// ---------------------------------------------------------------------------
__global__ __launch_bounds__(256, 1)
void proj3p_tc(const int* __restrict__ lens) {
    extern __shared__ char smem[];
    uint32_t sb = smem_u32(smem);
    (void)lens;

    const int z = 3 + blockIdx.z;
    const long m0 = (long)blockIdx.y * 128;
    const int  n0 = blockIdx.x * 128;

    GOps op;
    op.lda = DDIM; op.ldb = DDIM; op.mode = 3;
    h16 *Dh, *Dl;
    if (z == 3) { op.Ah = g_qh; op.Al = g_ql; op.Bh = g_Wh[3]; op.Bl = g_Wl[3];
                  Dh = g_qt0Th; Dl = g_qt0Tl; }
    else        { op.Ah = g_kh; op.Al = g_kl; op.Bh = g_Wh[4]; op.Bl = g_Wl[4];
                  Dh = g_kt0Th; Dl = g_kt0Tl; }
    op.Ah += m0 * DDIM; op.Al += m0 * DDIM;
    op.Bh += (long)n0 * DDIM; op.Bl += (long)n0 * DDIM;

    float acc[4][4][4] = {};
    run_gemm(&op, 1, 8, sb, acc);

    // transposed store via SMEM staging
    h16* Sh = reinterpret_cast<h16*>(smem);
    h16* Sl = reinterpret_cast<h16*>(smem + 34816);
    const int lane = threadIdx.x & 31, wid = threadIdx.x >> 5;
    const int wm = (wid >> 2) * 64, wn = (wid & 3) * 32;
    const int gr = lane >> 2, cp = (lane & 3) * 2;
    __syncthreads();
#pragma unroll
    for (int mi = 0; mi < 4; mi++)
#pragma unroll
        for (int ni = 0; ni < 4; ni++)
#pragma unroll
            for (int h = 0; h < 2; h++) {
                int r = wm + mi * 16 + gr + h * 8;
                int c = wn + ni * 8 + cp;
                float h0, l0, h1, l1;
                split1h(acc[mi][ni][h * 2]     * WINV, h0, l0);
                split1h(acc[mi][ni][h * 2 + 1] * WINV, h1, l1);
                Sh[(c    ) * 136 + r] = __float2half_rn(h0);
                Sh[(c + 1) * 136 + r] = __float2half_rn(h1);
                Sl[(c    ) * 136 + r] = __float2half_rn(l0);
                Sl[(c + 1) * 136 + r] = __float2half_rn(l1);
            }
    __syncthreads();
    const int t = threadIdx.x;
    const int d = t >> 1, half = t & 1;
    const int bb = (int)(m0 >> 10), lpos0 = (int)(m0 & 1023);
    long base = ((long)bb * DDIM + n0 + d) * LSEQ + lpos0 + half * 64;
    const uint4* sh = reinterpret_cast<const uint4*>(Sh + d * 136 + half * 64);
    const uint4* sl = reinterpret_cast<const uint4*>(Sl + d * 136 + half * 64);
    uint4* dh = reinterpret_cast<uint4*>(Dh + base);
    uint4* dl = reinterpret_cast<uint4*>(Dl + base);
#pragma unroll
    for (int j = 0; j < 8; j++) { dh[j] = sh[j]; dl[j] = sl[j]; }
}

// ---------------------------------------------------------------------------
// Stage B: qt/kt = dist @ qt0/kt0   (K = 1024, 3-product precision chain)
// ---------------------------------------------------------------------------
__global__ __launch_bounds__(256, 1)
void bmm_tc(const int* __restrict__ lens) {
    extern __shared__ char smem[];
    uint32_t sb = smem_u32(smem);

    const int z = blockIdx.z, b = z >> 1, isK = z & 1;
    const long m0 = (long)blockIdx.y * 128;
    if (isK) {
        const int len = lens[b];
        if ((int)m0 >= ((len + 127) & ~127)) return;
    }
    const h16* Bh = isK ? g_kt0Th : g_qt0Th;
    const h16* Bl = isK ? g_kt0Tl : g_qt0Tl;
    h16* Dh = isK ? g_kth : g_qth;
    h16* Dl = isK ? g_ktl : g_qtl;

    const int n0 = blockIdx.x * 128;

    GOps op;
    op.Ah = g_disth + (long)b * LSEQ * LSEQ + m0 * LSEQ;
    op.Al = g_distl + (long)b * LSEQ * LSEQ + m0 * LSEQ;
    op.lda = LSEQ; op.mode = 3;
    op.Bh = Bh + (long)b * LSEQ * DDIM + (long)n0 * LSEQ;
    op.Bl = Bl + (long)b * LSEQ * DDIM + (long)n0 * LSEQ;
    op.ldb = LSEQ;
    float acc[4][4][4] = {};
    run_gemm(&op, 1, 16, sb, acc);

    epi_hl(Dh + (long)b * LSEQ * DDIM, Dl + (long)b * LSEQ * DDIM, m0, n0, DDIM, acc, 1.0f);
}

// ---------------------------------------------------------------------------
// attn zero-fill for fully-masked tiles (independent of all GEMMs)
// ---------------------------------------------------------------------------
__global__ __launch_bounds__(256)
void attn_zero(float* __restrict__ out_attn, const int* __restrict__ lens) {
    const int b = blockIdx.z;
    const long m0 = (long)blockIdx.y * 128;
    const int  n0 = blockIdx.x * 128;
    if (n0 < lens[b]) return;
    const long arow0 = (long)b * LSEQ * LSEQ;
    const int t = threadIdx.x;
    const int r = t >> 1, half = t & 1;
    float4* dst = reinterpret_cast<float4*>(
        out_attn + arow0 + (m0 + r) * (long)LSEQ + n0 + half * 64);
    const float4 z4 = make_float4(0.f, 0.f, 0.f, 0.f);
#pragma unroll
    for (int j = 0; j < 16; j++) dst[j] = z4;
}

// ---------------------------------------------------------------------------
// Stage C: attn = tanh(((qp.kp' + qt.kt')/sqrt(D)) * mask) * mask
// op0 (qp.kp): 1-product (both hi-only); op1 (qt.kt): 3-product.
// ---------------------------------------------------------------------------
__global__ __launch_bounds__(256, 1)
void attn_tc(float* __restrict__ out_attn, const int* __restrict__ lens) {
    extern __shared__ char smem[];
    uint32_t sb = smem_u32(smem);

    const int b = blockIdx.z;
    const long m0 = (long)blockIdx.y * 128;
    const int  n0 = blockIdx.x * 128;
    const int  len = lens[b];
    if (n0 >= len) return;   // zero-filled by attn_zero
    const long arow0 = (long)b * LSEQ * LSEQ;

    const long po = (long)b * LSEQ * DDIM;
    GOps ops[2];
    ops[0].Ah = g_qph + po + m0 * DDIM; ops[0].Al = nullptr; ops[0].mode = 1;
    ops[0].Bh = g_kph + po + (long)n0 * DDIM; ops[0].Bl = nullptr;
    ops[0].lda = DDIM; ops[0].ldb = DDIM;
    ops[1].Ah = g_qth + po + m0 * DDIM; ops[1].Al = g_qtl + po + m0 * DDIM; ops[1].mode = 3;
    ops[1].Bh = g_kth + po + (long)n0 * DDIM; ops[1].Bl = g_ktl + po + (long)n0 * DDIM;
    ops[1].lda = DDIM; ops[1].ldb = DDIM;
    float acc[4][4][4] = {};
    run_gemm(ops, 2, 8, sb, acc);

    const float alpha = 0.044194173824159216f;   // 1/sqrt(512)
    const int lane = threadIdx.x & 31, wid = threadIdx.x >> 5;
    const int wm = (wid >> 2) * 64, wn = (wid & 3) * 32;
    const int gr = lane >> 2, cp = (lane & 3) * 2;

#pragma unroll
    for (int mi = 0; mi < 4; mi++)
#pragma unroll
        for (int ni = 0; ni < 4; ni++)
#pragma unroll
            for (int h = 0; h < 2; h++) {
                int r = wm + mi * 16 + gr + h * 8;
                int c = wn + ni * 8 + cp;
                int col = n0 + c;
                float t0 = (col     < len) ? tanh_fast(acc[mi][ni][h * 2]     * alpha) : 0.0f;
                float t1 = (col + 1 < len) ? tanh_fast(acc[mi][ni][h * 2 + 1] * alpha) : 0.0f;
                long base = arow0 + (m0 + r) * (long)LSEQ + col;
                *reinterpret_cast<float2*>(out_attn + base) = make_float2(t0, t1);
                *reinterpret_cast<uint32_t*>(g_ath + base) = pack_h2(t0, t1);
            }
}

// ---------------------------------------------------------------------------
// Stage D: out0 = attn @ vp   (1-product minimal; only ceil(len/64) K-chunks)
// ---------------------------------------------------------------------------
__global__ __launch_bounds__(256, 2)
void av_tc(const int* __restrict__ lens) {
    extern __shared__ char smem[];
    uint32_t sb = smem_u32(smem);

    const int b = blockIdx.z;
    const long m0 = (long)blockIdx.y * 128;
    const int  n0 = blockIdx.x * 128;
    const int  len = lens[b];
    const int  cpo = (len + 63) >> 6;

    GOps op;
    op.Ah = g_ath + (long)b * LSEQ * LSEQ + m0 * LSEQ;
    op.Al = nullptr; op.Bl = nullptr; op.mode = 1;
    op.lda = LSEQ;
    op.Bh = g_vpTh + (long)b * LSEQ * DDIM + (long)n0 * LSEQ;
    op.ldb = LSEQ;
    float acc[4][4][4] = {};
    run_gemm_1(op, cpo, sb, acc);

    epi_h(g_o0h + (long)b * LSEQ * DDIM, m0, n0, DDIM, acc, 1.0f);
}

// ---------------------------------------------------------------------------
// Stage E: fc = out0 @ Wfc' + residual(q)  (2-product compact)
// ---------------------------------------------------------------------------
__global__ __launch_bounds__(256, 1)
void fc_tc(const float* __restrict__ q) {
    extern __shared__ char smem[];
    uint32_t sb = smem_u32(smem);

    const long m0 = (long)blockIdx.y * 128;
    const int  n0 = blockIdx.x * 128;

    GOps op;
    op.Ah = g_o0h + m0 * DDIM; op.Al = nullptr; op.mode = 2; op.lda = DDIM;
    op.Bh = g_Wh[5] + (long)n0 * DDIM; op.Bl = g_Wl[5] + (long)n0 * DDIM; op.ldb = DDIM;
    float acc[4][4][4] = {};
    run_gemm_c(op, 8, sb, acc);

    const int lane = threadIdx.x & 31, wid = threadIdx.x >> 5;
    const int wm = (wid >> 2) * 64, wn = (wid & 3) * 32;
    const int gr = lane >> 2, cp = (lane & 3) * 2;
#pragma unroll
    for (int mi = 0; mi < 4; mi++)
#pragma unroll
        for (int ni = 0; ni < 4; ni++)
#pragma unroll
            for (int h = 0; h < 2; h++) {
                int r = wm + mi * 16 + gr + h * 8;
                int c = wn + ni * 8 + cp;
                long base = (m0 + r) * (long)DDIM + n0 + c;
                float2 rv = *reinterpret_cast<const float2*>(q + base);
                *reinterpret_cast<float2*>(g_fc + base) =
                    make_float2(acc[mi][ni][h * 2] * WINV + rv.x,
                                acc[mi][ni][h * 2 + 1] * WINV + rv.y);
            }
}

// ---------------------------------------------------------------------------
// fp32 -> fp16 hi/lo splits
// ---------------------------------------------------------------------------
__global__ __launch_bounds__(256)
void split_qkv(const float* __restrict__ q, const float* __restrict__ k,
               const float* __restrict__ v) {
    const int y = blockIdx.y;
    long i = (long)blockIdx.x * 256 + threadIdx.x;
    const float* s = (y == 0) ? q : (y == 1) ? k : v;
    float4 vv = reinterpret_cast<const float4*>(s)[i];
    float hx, lx, hy, ly, hz, lz, hw, lw;
    split1h(vv.x, hx, lx); split1h(vv.y, hy, ly);
    split1h(vv.z, hz, lz); split1h(vv.w, hw, lw);
    uint2 hh = make_uint2(pack_h2(hx, hy), pack_h2(hz, hw));
    uint2 ll = make_uint2(pack_h2(lx, ly), pack_h2(lz, lw));
    if (y == 0)      { reinterpret_cast<uint2*>(g_qh)[i] = hh; reinterpret_cast<uint2*>(g_ql)[i] = ll; }
    else if (y == 1) { reinterpret_cast<uint2*>(g_kh)[i] = hh; reinterpret_cast<uint2*>(g_kl)[i] = ll; }
    else             { reinterpret_cast<uint2*>(g_vh)[i] = hh; }
}

__global__ __launch_bounds__(256)
void split_dist(const float* __restrict__ d) {
    long i = (long)blockIdx.x * 256 + threadIdx.x;
    float4 vv = reinterpret_cast<const float4*>(d)[i];
    float hx, lx, hy, ly, hz, lz, hw, lw;
    split1h(vv.x, hx, lx); split1h(vv.y, hy, ly);
    split1h(vv.z, hz, lz); split1h(vv.w, hw, lw);
    reinterpret_cast<uint2*>(g_disth)[i] = make_uint2(pack_h2(hx, hy), pack_h2(hz, hw));
    reinterpret_cast<uint2*>(g_distl)[i] = make_uint2(pack_h2(lx, ly), pack_h2(lz, lw));
}

__global__ __launch_bounds__(256)
void split_w(const float* __restrict__ w0, const float* __restrict__ w1,
             const float* __restrict__ w2, const float* __restrict__ w3,
             const float* __restrict__ w4, const float* __restrict__ w5) {
    const float* s; int wi = blockIdx.y;
    switch (wi) {
        case 0: s = w0; break; case 1: s = w1; break; case 2: s = w2; break;
        case 3: s = w3; break; case 4: s = w4; break; default: s = w5; break;
    }
    long i = (long)blockIdx.x * 256 + threadIdx.x;
    float4 vv = reinterpret_cast<const float4*>(s)[i];
    float hx, lx, hy, ly, hz, lz, hw, lw;
    split1h(vv.x * WSC, hx, lx); split1h(vv.y * WSC, hy, ly);
    split1h(vv.z * WSC, hz, lz); split1h(vv.w * WSC, hw, lw);
    reinterpret_cast<uint2*>(g_Wh[wi])[i] = make_uint2(pack_h2(hx, hy), pack_h2(hz, hw));
    reinterpret_cast<uint2*>(g_Wl[wi])[i] = make_uint2(pack_h2(lx, ly), pack_h2(lz, lw));
}

// ---------------------------------------------------------------------------
// LayerNorm over D=512
// ---------------------------------------------------------------------------
__global__ __launch_bounds__(128)
void ln_kernel(const float* __restrict__ gamma, const float* __restrict__ beta,
               float* __restrict__ out) {
    const long row = blockIdx.x;
    const int  t   = threadIdx.x;
    float4 v = reinterpret_cast<const float4*>(g_fc)[row * 128 + t];
    float s  = v.x + v.y + v.z + v.w;
    float s2 = v.x * v.x + v.y * v.y + v.z * v.z + v.w * v.w;
#pragma unroll
    for (int o = 16; o; o >>= 1) {
        s  += __shfl_xor_sync(0xffffffffu, s,  o);
        s2 += __shfl_xor_sync(0xffffffffu, s2, o);
    }
    __shared__ float ss[4], ss2[4];
    if ((t & 31) == 0) { ss[t >> 5] = s; ss2[t >> 5] = s2; }
    __syncthreads();
    s  = ss[0] + ss[1] + ss[2] + ss[3];
    s2 = ss2[0] + ss2[1] + ss2[2] + ss2[3];
    const float mu  = s * (1.0f / 512.0f);
    const float var = s2 * (1.0f / 512.0f) - mu * mu;
    const float inv = rsqrtf(var + 1e-6f);
    float4 g  = reinterpret_cast<const float4*>(gamma)[t];
    float4 be = reinterpret_cast<const float4*>(beta)[t];
    float4 o;
    o.x = (v.x - mu) * inv * g.x + be.x;
    o.y = (v.y - mu) * inv * g.y + be.y;
    o.z = (v.z - mu) * inv * g.z + be.z;
    o.w = (v.w - mu) * inv * g.w + be.w;
    reinterpret_cast<float4*>(out)[row * 128 + t] = o;
}

// ---------------------------------------------------------------------------
extern "C" void kernel_launch(void* const* d_in, const int* in_sizes, int n_in,
                              void* d_out, int out_size)
{
    (void)in_sizes; (void)n_in; (void)out_size;
    const float* q     = (const float*)d_in[0];
    const float* k     = (const float*)d_in[1];
    const float* v     = (const float*)d_in[2];
    const int*   lens  = (const int*)  d_in[3];
    const float* dist  = (const float*)d_in[4];
    const float* Wq    = (const float*)d_in[5];
    const float* Wk    = (const float*)d_in[6];
    const float* Wv    = (const float*)d_in[7];
    const float* Wqt   = (const float*)d_in[8];
    const float* Wkt   = (const float*)d_in[9];
    const float* Wfc   = (const float*)d_in[10];
    const float* gamma = (const float*)d_in[11];
    const float* beta  = (const float*)d_in[12];

    float* out_ln   = (float*)d_out;                       // [B, L, D]
    float* out_attn = out_ln + (size_t)BB * LSEQ * DDIM;   // [B, L, L]

    static cudaStream_t s1 = nullptr;
    static cudaEvent_t ev1 = nullptr, ev2 = nullptr;
    if (!s1) {
        cudaStreamCreateWithFlags(&s1, cudaStreamNonBlocking);
        cudaEventCreateWithFlags(&ev1, cudaEventDisableTiming);
        cudaEventCreateWithFlags(&ev2, cudaEventDisableTiming);
    }

    cudaFuncSetAttribute(proj2p_tc, cudaFuncAttributeMaxDynamicSharedMemorySize, SMEM_COMPACT);
    cudaFuncSetAttribute(proj3p_tc, cudaFuncAttributeMaxDynamicSharedMemorySize, SMEM_BIG);
    cudaFuncSetAttribute(bmm_tc,    cudaFuncAttributeMaxDynamicSharedMemorySize, SMEM_BIG);
    cudaFuncSetAttribute(attn_tc,   cudaFuncAttributeMaxDynamicSharedMemorySize, SMEM_BIG);
    cudaFuncSetAttribute(av_tc,     cudaFuncAttributeMaxDynamicSharedMemorySize, SMEM_MIN);
    cudaFuncSetAttribute(fc_tc,     cudaFuncAttributeMaxDynamicSharedMemorySize, SMEM_COMPACT);

    // main: input splits that everything downstream needs
    split_qkv <<<dim3(NQ / 4 / 256, 3), 256>>>(q, k, v);
    split_w   <<<dim3(NW / 4 / 256, 6), 256>>>(Wq, Wk, Wv, Wqt, Wkt, Wfc);

    // fork: cheap independent work on s1 (proj2p + attn zero-fill)
    cudaEventRecord(ev1, 0);
    cudaStreamWaitEvent(s1, ev1, 0);
    proj2p_tc<<<dim3(4, 128, 3), 256, SMEM_COMPACT, s1>>>(lens);
    attn_zero<<<dim3(8, 8, 16), 256, 0, s1>>>(out_attn, lens);
    cudaEventRecord(ev2, s1);

    // main: critical chain
    split_dist<<<NATT / 4 / 256, 256>>>(dist);
    proj3p_tc<<<dim3(4, 128, 2), 256, SMEM_BIG>>>(lens);
    bmm_tc   <<<dim3(4, 8, 32),  256, SMEM_BIG>>>(lens);

    // join, then serial tail
    cudaStreamWaitEvent(0, ev2, 0);
    attn_tc<<<dim3(8, 8, 16),  256, SMEM_BIG>>>(out_attn, lens);
    av_tc  <<<dim3(4, 8, 16),  256, SMEM_MIN>>>(lens);
    fc_tc  <<<dim3(4, 128, 1), 256, SMEM_COMPACT>>>(q);
    ln_kernel<<<BB * LSEQ, 128>>>(gamma, beta, out_ln);
}

// round 14
// speedup vs baseline: 1.2146x; 1.0961x over previous
#include <cuda_runtime.h>
#include <cuda_fp16.h>
#include <stdint.h>
#include <math.h>

#define BB   16
#define LSEQ 1024
#define DDIM 512
typedef __half h16;

#define NQ   8388608    // B*L*D
#define NATT 16777216   // B*L*L
#define NW   262144     // D*D
#define WSC  32.0f      // W pre-scale (keeps W-lo out of fp16 subnormals)
#define WINV 0.03125f

// ---------------- scratch (device globals; no allocation allowed) ----------
__device__ __align__(16) h16 g_qh[NQ],    g_ql[NQ];
__device__ __align__(16) h16 g_kh[NQ],    g_kl[NQ];
__device__ __align__(16) h16 g_vh[NQ];                     // v: hi only
__device__ __align__(16) h16 g_disth[NATT], g_distl[NATT];
__device__ __align__(16) h16 g_Wh[6][NW], g_Wl[6][NW];     // 32*W split
__device__ __align__(16) h16 g_qph[NQ];                    // hi only
__device__ __align__(16) h16 g_kph[NQ];                    // hi only (1p attn op0)
__device__ __align__(16) h16 g_vpTh[NQ];                   // [b][d][m], hi only (1p av)
__device__ __align__(16) h16 g_qt0Th[NQ], g_qt0Tl[NQ];     // [b][d][m], B in bmm
__device__ __align__(16) h16 g_kt0Th[NQ], g_kt0Tl[NQ];
__device__ __align__(16) h16 g_qth[NQ],   g_qtl[NQ];       // A in attn op1 (3p)
__device__ __align__(16) h16 g_kth[NQ],   g_ktl[NQ];       // B in attn op1
__device__ __align__(16) h16 g_ath[NATT];                  // hi only (A in av)
__device__ __align__(16) h16 g_o0h[NQ];                    // hi only (A in fc 1p)
__device__ float g_fc[NQ];

// ---------------- helpers ---------------------------------------------------
__device__ __forceinline__ uint32_t smem_u32(const void* p) {
    return (uint32_t)__cvta_generic_to_shared(p);
}
__device__ __forceinline__ uint32_t pack_h2(float a, float b) {
    __half2 t = __floats2half2_rn(a, b);
    return *reinterpret_cast<uint32_t*>(&t);
}
__device__ __forceinline__ void split1h(float v, float& h, float& l) {
    h = __half2float(__float2half_rn(v));
    l = v - h;
}
__device__ __forceinline__ float tanh_fast(float x) {
    float y;
    asm("tanh.approx.f32 %0, %1;" : "=f"(y) : "f"(x));
    return y;
}

// Big (up-to-3p) layout: Ah(16K) Al(16K) Bh(16K) Bl(16K) = 64KB x 2 stages
#define BUF_SZ       65536
#define SMEM_BIG     (2 * BUF_SZ)
// Minimal (1p) layout: Ah(16K) Bh(16K) = 32KB x 2 stages
#define MBUF_SZ      32768
#define SMEM_MIN     (2 * MBUF_SZ)

__device__ __forceinline__ uint32_t swz(uint32_t base, int row, int cb) {
    uint32_t off = ((uint32_t)row << 7) + (uint32_t)cb;
    return base + (off ^ ((off >> 3) & 0x70));
}
__device__ __forceinline__ uint32_t a_addr(uint32_t base, int row0, int kb, int lane) {
    int mat = lane >> 3;
    return swz(base, row0 + (lane & 7) + ((mat & 1) << 3), kb + ((mat >> 1) << 4));
}
__device__ __forceinline__ uint32_t b_addr(uint32_t base, int n0, int kb, int lane) {
    int mat = lane >> 3;
    return swz(base, n0 + (lane & 7) + ((mat >> 1) << 3), kb + ((mat & 1) << 4));
}
__device__ __forceinline__ void ldsm4(uint32_t a, uint32_t* r) {
    asm volatile("ldmatrix.sync.aligned.m8n8.x4.shared.b16 {%0,%1,%2,%3}, [%4];"
                 : "=r"(r[0]), "=r"(r[1]), "=r"(r[2]), "=r"(r[3]) : "r"(a));
}
__device__ __forceinline__ void mma16816(float* d, const uint32_t* a, const uint32_t* b) {
    asm volatile(
        "mma.sync.aligned.m16n8k16.row.col.f32.f16.f16.f32 "
        "{%0,%1,%2,%3}, {%4,%5,%6,%7}, {%8,%9}, {%0,%1,%2,%3};"
        : "+f"(d[0]), "+f"(d[1]), "+f"(d[2]), "+f"(d[3])
        : "r"(a[0]), "r"(a[1]), "r"(a[2]), "r"(a[3]), "r"(b[0]), "r"(b[1]));
}

// mode: 1 = Ah*Bh; 2 = Ah*(Bh+Bl); 3 = 2 + Al*Bh
struct GOps { const h16 *Ah, *Al, *Bh, *Bl; int lda, ldb, mode; };

// async-copy one 128-row x 64-h16 (128B/row) tile into swizzled SMEM
__device__ __forceinline__ void load_tile_async(const h16* __restrict__ g, int ld,
                                                uint32_t sdst) {
    int t = threadIdx.x;
#pragma unroll
    for (int i = 0; i < 4; i++) {
        int u   = t + (i << 8);
        int row = u >> 3;
        int seg = (u & 7) << 4;
        const char* src = reinterpret_cast<const char*>(g + (long)row * ld) + seg;
        asm volatile("cp.async.cg.shared.global [%0], [%1], 16;"
                     :: "r"(swz(sdst, row, seg)), "l"(src));
    }
}

// ===== big (up-to-3p) path: proj3p / bmm / attn =====
__device__ __forceinline__ void issue_chunk(const GOps& o, int k0, uint32_t buf) {
    load_tile_async(o.Ah + k0, o.lda, buf);
    if (o.mode == 3) load_tile_async(o.Al + k0, o.lda, buf + 16384);
    load_tile_async(o.Bh + k0, o.ldb, buf + 32768);
    if (o.mode >= 2) load_tile_async(o.Bl + k0, o.ldb, buf + 49152);
    asm volatile("cp.async.commit_group;");
}
__device__ __forceinline__ void compute_chunk(uint32_t buf, int lane, int wm, int wn,
                                              float acc[4][4][4], int mode) {
#pragma unroll
    for (int ks = 0; ks < 4; ks++) {
        const int kb = ks * 32;
        uint32_t aH[4][4], aL[4][4], bH[8], bL[8];
#pragma unroll
        for (int mi = 0; mi < 4; mi++) ldsm4(a_addr(buf, wm + mi * 16, kb, lane), aH[mi]);
        if (mode == 3) {
#pragma unroll
            for (int mi = 0; mi < 4; mi++)
                ldsm4(a_addr(buf + 16384, wm + mi * 16, kb, lane), aL[mi]);
        }
        ldsm4(b_addr(buf + 32768, wn,      kb, lane), bH);
        ldsm4(b_addr(buf + 32768, wn + 16, kb, lane), bH + 4);
        if (mode >= 2) {
            ldsm4(b_addr(buf + 49152, wn,      kb, lane), bL);
            ldsm4(b_addr(buf + 49152, wn + 16, kb, lane), bL + 4);
        }
#pragma unroll
        for (int mi = 0; mi < 4; mi++)
#pragma unroll
            for (int ni = 0; ni < 4; ni++)
                mma16816(acc[mi][ni], aH[mi], bH + ni * 2);
        if (mode >= 2) {
#pragma unroll
            for (int mi = 0; mi < 4; mi++)
#pragma unroll
                for (int ni = 0; ni < 4; ni++)
                    mma16816(acc[mi][ni], aH[mi], bL + ni * 2);
        }
        if (mode == 3) {
#pragma unroll
            for (int mi = 0; mi < 4; mi++)
#pragma unroll
                for (int ni = 0; ni < 4; ni++)
                    mma16816(acc[mi][ni], aL[mi], bH + ni * 2);
        }
    }
}
__device__ __forceinline__ void run_gemm(const GOps* ops, int nops, int cpo,
                                         uint32_t sb, float acc[4][4][4]) {
    const int lane = threadIdx.x & 31, wid = threadIdx.x >> 5;
    const int wm = (wid >> 2) * 64, wn = (wid & 3) * 32;
    const int C = nops * cpo;

    issue_chunk(ops[0], 0, sb);
    for (int c = 0; c < C; c++) {
        if (c + 1 < C) {
            const GOps& o = ops[(c + 1) / cpo];
            issue_chunk(o, ((c + 1) % cpo) * 64, sb + ((c + 1) & 1) * BUF_SZ);
            asm volatile("cp.async.wait_group 1;" ::: "memory");
        } else {
            asm volatile("cp.async.wait_group 0;" ::: "memory");
        }
        __syncthreads();
        compute_chunk(sb + (c & 1) * BUF_SZ, lane, wm, wn, acc, ops[c / cpo].mode);
        __syncthreads();
    }
}

// ===== minimal (1p) path: Ah / Bh(+16K), 32KB stages =====
__device__ __forceinline__ void issue_chunk_1(const GOps& o, int k0, uint32_t buf) {
    load_tile_async(o.Ah + k0, o.lda, buf);
    load_tile_async(o.Bh + k0, o.ldb, buf + 16384);
    asm volatile("cp.async.commit_group;");
}
__device__ __forceinline__ void compute_chunk_1(uint32_t buf, int lane, int wm, int wn,
                                                float acc[4][4][4]) {
#pragma unroll
    for (int ks = 0; ks < 4; ks++) {
        const int kb = ks * 32;
        uint32_t aH[4][4], bH[8];
#pragma unroll
        for (int mi = 0; mi < 4; mi++) ldsm4(a_addr(buf, wm + mi * 16, kb, lane), aH[mi]);
        ldsm4(b_addr(buf + 16384, wn,      kb, lane), bH);
        ldsm4(b_addr(buf + 16384, wn + 16, kb, lane), bH + 4);
#pragma unroll
        for (int mi = 0; mi < 4; mi++)
#pragma unroll
            for (int ni = 0; ni < 4; ni++)
                mma16816(acc[mi][ni], aH[mi], bH + ni * 2);
    }
}
__device__ __forceinline__ void run_gemm_1(const GOps& op, int cpo,
                                           uint32_t sb, float acc[4][4][4]) {
    const int lane = threadIdx.x & 31, wid = threadIdx.x >> 5;
    const int wm = (wid >> 2) * 64, wn = (wid & 3) * 32;

    issue_chunk_1(op, 0, sb);
    for (int c = 0; c < cpo; c++) {
        if (c + 1 < cpo) {
            issue_chunk_1(op, (c + 1) * 64, sb + ((c + 1) & 1) * MBUF_SZ);
            asm volatile("cp.async.wait_group 1;" ::: "memory");
        } else {
            asm volatile("cp.async.wait_group 0;" ::: "memory");
        }
        __syncthreads();
        compute_chunk_1(sb + (c & 1) * MBUF_SZ, lane, wm, wn, acc);
        __syncthreads();
    }
}

// epilogue helpers
__device__ __forceinline__ void epi_hl(h16* Dh, h16* Dl, long m0, int n0, int ld,
                                       const float acc[4][4][4], float sc) {
    const int lane = threadIdx.x & 31, wid = threadIdx.x >> 5;
    const int wm = (wid >> 2) * 64, wn = (wid & 3) * 32;
    const int gr = lane >> 2, cp = (lane & 3) * 2;
#pragma unroll
    for (int mi = 0; mi < 4; mi++)
#pragma unroll
        for (int ni = 0; ni < 4; ni++)
#pragma unroll
            for (int h = 0; h < 2; h++) {
                int r = wm + mi * 16 + gr + h * 8;
                int c = wn + ni * 8 + cp;
                float h0, l0, h1, l1;
                split1h(acc[mi][ni][h * 2]     * sc, h0, l0);
                split1h(acc[mi][ni][h * 2 + 1] * sc, h1, l1);
                long base = (m0 + r) * (long)ld + n0 + c;
                *reinterpret_cast<uint32_t*>(Dh + base) = pack_h2(h0, h1);
                *reinterpret_cast<uint32_t*>(Dl + base) = pack_h2(l0, l1);
            }
}
__device__ __forceinline__ void epi_h(h16* Dh, long m0, int n0, int ld,
                                      const float acc[4][4][4], float sc) {
    const int lane = threadIdx.x & 31, wid = threadIdx.x >> 5;
    const int wm = (wid >> 2) * 64, wn = (wid & 3) * 32;
    const int gr = lane >> 2, cp = (lane & 3) * 2;
#pragma unroll
    for (int mi = 0; mi < 4; mi++)
#pragma unroll
        for (int ni = 0; ni < 4; ni++)
#pragma unroll
            for (int h = 0; h < 2; h++) {
                int r = wm + mi * 16 + gr + h * 8;
                int c = wn + ni * 8 + cp;
                long base = (m0 + r) * (long)ld + n0 + c;
                *reinterpret_cast<uint32_t*>(Dh + base) =
                    pack_h2(acc[mi][ni][h * 2] * sc, acc[mi][ni][h * 2 + 1] * sc);
            }
}

// ---------------------------------------------------------------------------
// proj1p: z = 0 qp, 1 kp, 2 vpT  (1-product X*Wh; hi-only outputs)
// ---------------------------------------------------------------------------
__global__ __launch_bounds__(256, 2)
void proj1p_tc(const int* __restrict__ lens) {
    extern __shared__ char smem[];
    uint32_t sb = smem_u32(smem);

    const int z = blockIdx.z;
    const long m0 = (long)blockIdx.y * 128;

    if (z == 1 || z == 2) {
        const int len = lens[(int)(m0 >> 10)];
        const int lm  = (int)(m0 & 1023);
        const int lim = (z == 1) ? ((len + 127) & ~127) : ((len + 63) & ~63);
        if (lm >= lim) return;
    }

    const int n0 = blockIdx.x * 128;
    GOps op;
    op.lda = DDIM; op.ldb = DDIM; op.Al = nullptr; op.Bl = nullptr; op.mode = 1;
    h16* Dh;
    switch (z) {
        case 0: op.Ah = g_qh; op.Bh = g_Wh[0]; Dh = g_qph;  break;
        case 1: op.Ah = g_kh; op.Bh = g_Wh[1]; Dh = g_kph;  break;
        default:op.Ah = g_vh; op.Bh = g_Wh[2]; Dh = g_vpTh; break;
    }
    op.Ah += m0 * DDIM;
    op.Bh += (long)n0 * DDIM;

    float acc[4][4][4] = {};
    run_gemm_1(op, 8, sb, acc);

    if (z != 2) { epi_h(Dh, m0, n0, DDIM, acc, WINV); return; }

    // z == 2: transposed hi-only store via SMEM staging (34816 B <= 64KB)
    h16* Sh = reinterpret_cast<h16*>(smem);
    const int lane = threadIdx.x & 31, wid = threadIdx.x >> 5;
    const int wm = (wid >> 2) * 64, wn = (wid & 3) * 32;
    const int gr = lane >> 2, cp = (lane & 3) * 2;
    __syncthreads();
#pragma unroll
    for (int mi = 0; mi < 4; mi++)
#pragma unroll
        for (int ni = 0; ni < 4; ni++)
#pragma unroll
            for (int h = 0; h < 2; h++) {
                int r = wm + mi * 16 + gr + h * 8;
                int c = wn + ni * 8 + cp;
                Sh[(c    ) * 136 + r] = __float2half_rn(acc[mi][ni][h * 2]     * WINV);
                Sh[(c + 1) * 136 + r] = __float2half_rn(acc[mi][ni][h * 2 + 1] * WINV);
            }
    __syncthreads();
    const int t = threadIdx.x;
    const int d = t >> 1, half = t & 1;
    const int bb = (int)(m0 >> 10), lpos0 = (int)(m0 & 1023);
    long base = ((long)bb * DDIM + n0 + d) * LSEQ + lpos0 + half * 64;
    const uint4* sh = reinterpret_cast<const uint4*>(Sh + d * 136 + half * 64);
    uint4* dh = reinterpret_cast<uint4*>(Dh + base);
#pragma unroll
    for (int j = 0; j < 8; j++) dh[j] = sh[j];
}

// ---------------------------------------------------------------------------
// proj3p: z = 3 qt0T, 4 kt0T  (3-product precision chain, big SMEM)
// ---------------------------------------------------------------------------
__global__ __launch_bounds__(256, 1)
void proj3p_tc(const int* __restrict__ lens) {
    extern __shared__ char smem[];
    uint32_t sb = smem_u32(smem);
    (void)lens;

    const int z = 3 + blockIdx.z;
    const long m0 = (long)blockIdx.y * 128;
    const int  n0 = blockIdx.x * 128;

    GOps op;
    op.lda = DDIM; op.ldb = DDIM; op.mode = 3;
    h16 *Dh, *Dl;
    if (z == 3) { op.Ah = g_qh; op.Al = g_ql; op.Bh = g_Wh[3]; op.Bl = g_Wl[3];
                  Dh = g_qt0Th; Dl = g_qt0Tl; }
    else        { op.Ah = g_kh; op.Al = g_kl; op.Bh = g_Wh[4]; op.Bl = g_Wl[4];
                  Dh = g_kt0Th; Dl = g_kt0Tl; }
    op.Ah += m0 * DDIM; op.Al += m0 * DDIM;
    op.Bh += (long)n0 * DDIM; op.Bl += (long)n0 * DDIM;

    float acc[4][4][4] = {};
    run_gemm(&op, 1, 8, sb, acc);

    // transposed store via SMEM staging
    h16* Sh = reinterpret_cast<h16*>(smem);
    h16* Sl = reinterpret_cast<h16*>(smem + 34816);
    const int lane = threadIdx.x & 31, wid = threadIdx.x >> 5;
    const int wm = (wid >> 2) * 64, wn = (wid & 3) * 32;
    const int gr = lane >> 2, cp = (lane & 3) * 2;
    __syncthreads();
#pragma unroll
    for (int mi = 0; mi < 4; mi++)
#pragma unroll
        for (int ni = 0; ni < 4; ni++)
#pragma unroll
            for (int h = 0; h < 2; h++) {
                int r = wm + mi * 16 + gr + h * 8;
                int c = wn + ni * 8 + cp;
                float h0, l0, h1, l1;
                split1h(acc[mi][ni][h * 2]     * WINV, h0, l0);
                split1h(acc[mi][ni][h * 2 + 1] * WINV, h1, l1);
                Sh[(c    ) * 136 + r] = __float2half_rn(h0);
                Sh[(c + 1) * 136 + r] = __float2half_rn(h1);
                Sl[(c    ) * 136 + r] = __float2half_rn(l0);
                Sl[(c + 1) * 136 + r] = __float2half_rn(l1);
            }
    __syncthreads();
    const int t = threadIdx.x;
    const int d = t >> 1, half = t & 1;
    const int bb = (int)(m0 >> 10), lpos0 = (int)(m0 & 1023);
    long base = ((long)bb * DDIM + n0 + d) * LSEQ + lpos0 + half * 64;
    const uint4* sh = reinterpret_cast<const uint4*>(Sh + d * 136 + half * 64);
    const uint4* sl = reinterpret_cast<const uint4*>(Sl + d * 136 + half * 64);
    uint4* dh = reinterpret_cast<uint4*>(Dh + base);
    uint4* dl = reinterpret_cast<uint4*>(Dl + base);
#pragma unroll
    for (int j = 0; j < 8; j++) { dh[j] = sh[j]; dl[j] = sl[j]; }
}

// ---------------------------------------------------------------------------
// Stage B: qt/kt = dist @ qt0/kt0   (K = 1024, 3-product precision chain)
// ---------------------------------------------------------------------------
__global__ __launch_bounds__(256, 1)
void bmm_tc(const int* __restrict__ lens) {
    extern __shared__ char smem[];
    uint32_t sb = smem_u32(smem);

    const int z = blockIdx.z, b = z >> 1, isK = z & 1;
    const long m0 = (long)blockIdx.y * 128;
    if (isK) {
        const int len = lens[b];
        if ((int)m0 >= ((len + 127) & ~127)) return;
    }
    const h16* Bh = isK ? g_kt0Th : g_qt0Th;
    const h16* Bl = isK ? g_kt0Tl : g_qt0Tl;
    h16* Dh = isK ? g_kth : g_qth;
    h16* Dl = isK ? g_ktl : g_qtl;

    const int n0 = blockIdx.x * 128;

    GOps op;
    op.Ah = g_disth + (long)b * LSEQ * LSEQ + m0 * LSEQ;
    op.Al = g_distl + (long)b * LSEQ * LSEQ + m0 * LSEQ;
    op.lda = LSEQ; op.mode = 3;
    op.Bh = Bh + (long)b * LSEQ * DDIM + (long)n0 * LSEQ;
    op.Bl = Bl + (long)b * LSEQ * DDIM + (long)n0 * LSEQ;
    op.ldb = LSEQ;
    float acc[4][4][4] = {};
    run_gemm(&op, 1, 16, sb, acc);

    epi_hl(Dh + (long)b * LSEQ * DDIM, Dl + (long)b * LSEQ * DDIM, m0, n0, DDIM, acc, 1.0f);
}

// ---------------------------------------------------------------------------
// attn zero-fill for fully-masked tiles (independent of all GEMMs)
// ---------------------------------------------------------------------------
__global__ __launch_bounds__(256)
void attn_zero(float* __restrict__ out_attn, const int* __restrict__ lens) {
    const int b = blockIdx.z;
    const long m0 = (long)blockIdx.y * 128;
    const int  n0 = blockIdx.x * 128;
    if (n0 < lens[b]) return;
    const long arow0 = (long)b * LSEQ * LSEQ;
    const int t = threadIdx.x;
    const int r = t >> 1, half = t & 1;
    float4* dst = reinterpret_cast<float4*>(
        out_attn + arow0 + (m0 + r) * (long)LSEQ + n0 + half * 64);
    const float4 z4 = make_float4(0.f, 0.f, 0.f, 0.f);
#pragma unroll
    for (int j = 0; j < 16; j++) dst[j] = z4;
}

// ---------------------------------------------------------------------------
// Stage C: attn = tanh(((qp.kp' + qt.kt')/sqrt(D)) * mask) * mask
// op0 (qp.kp): 1-product; op1 (qt.kt): 3-product.
// ---------------------------------------------------------------------------
__global__ __launch_bounds__(256, 1)
void attn_tc(float* __restrict__ out_attn, const int* __restrict__ lens) {
    extern __shared__ char smem[];
    uint32_t sb = smem_u32(smem);

    const int b = blockIdx.z;
    const long m0 = (long)blockIdx.y * 128;
    const int  n0 = blockIdx.x * 128;
    const int  len = lens[b];
    if (n0 >= len) return;   // zero-filled by attn_zero
    const long arow0 = (long)b * LSEQ * LSEQ;

    const long po = (long)b * LSEQ * DDIM;
    GOps ops[2];
    ops[0].Ah = g_qph + po + m0 * DDIM; ops[0].Al = nullptr; ops[0].mode = 1;
    ops[0].Bh = g_kph + po + (long)n0 * DDIM; ops[0].Bl = nullptr;
    ops[0].lda = DDIM; ops[0].ldb = DDIM;
    ops[1].Ah = g_qth + po + m0 * DDIM; ops[1].Al = g_qtl + po + m0 * DDIM; ops[1].mode = 3;
    ops[1].Bh = g_kth + po + (long)n0 * DDIM; ops[1].Bl = g_ktl + po + (long)n0 * DDIM;
    ops[1].lda = DDIM; ops[1].ldb = DDIM;
    float acc[4][4][4] = {};
    run_gemm(ops, 2, 8, sb, acc);

    const float alpha = 0.044194173824159216f;   // 1/sqrt(512)
    const int lane = threadIdx.x & 31, wid = threadIdx.x >> 5;
    const int wm = (wid >> 2) * 64, wn = (wid & 3) * 32;
    const int gr = lane >> 2, cp = (lane & 3) * 2;

#pragma unroll
    for (int mi = 0; mi < 4; mi++)
#pragma unroll
        for (int ni = 0; ni < 4; ni++)
#pragma unroll
            for (int h = 0; h < 2; h++) {
                int r = wm + mi * 16 + gr + h * 8;
                int c = wn + ni * 8 + cp;
                int col = n0 + c;
                float t0 = (col     < len) ? tanh_fast(acc[mi][ni][h * 2]     * alpha) : 0.0f;
                float t1 = (col + 1 < len) ? tanh_fast(acc[mi][ni][h * 2 + 1] * alpha) : 0.0f;
                long base = arow0 + (m0 + r) * (long)LSEQ + col;
                *reinterpret_cast<float2*>(out_attn + base) = make_float2(t0, t1);
                *reinterpret_cast<uint32_t*>(g_ath + base) = pack_h2(t0, t1);
            }
}

// ---------------------------------------------------------------------------
// Stage D: out0 = attn @ vp   (1-product minimal; only ceil(len/64) K-chunks)
// ---------------------------------------------------------------------------
__global__ __launch_bounds__(256, 2)
void av_tc(const int* __restrict__ lens) {
    extern __shared__ char smem[];
    uint32_t sb = smem_u32(smem);

    const int b = blockIdx.z;
    const long m0 = (long)blockIdx.y * 128;
    const int  n0 = blockIdx.x * 128;
    const int  len = lens[b];
    const int  cpo = (len + 63) >> 6;

    GOps op;
    op.Ah = g_ath + (long)b * LSEQ * LSEQ + m0 * LSEQ;
    op.Al = nullptr; op.Bl = nullptr; op.mode = 1;
    op.lda = LSEQ;
    op.Bh = g_vpTh + (long)b * LSEQ * DDIM + (long)n0 * LSEQ;
    op.ldb = LSEQ;
    float acc[4][4][4] = {};
    run_gemm_1(op, cpo, sb, acc);

    epi_h(g_o0h + (long)b * LSEQ * DDIM, m0, n0, DDIM, acc, 1.0f);
}

// ---------------------------------------------------------------------------
// Stage E: fc = out0 @ Wfc' + residual(q)  (1-product minimal)
// ---------------------------------------------------------------------------
__global__ __launch_bounds__(256, 2)
void fc_tc(const float* __restrict__ q) {
    extern __shared__ char smem[];
    uint32_t sb = smem_u32(smem);

    const long m0 = (long)blockIdx.y * 128;
    const int  n0 = blockIdx.x * 128;

    GOps op;
    op.Ah = g_o0h + m0 * DDIM; op.Al = nullptr; op.Bl = nullptr; op.mode = 1;
    op.lda = DDIM;
    op.Bh = g_Wh[5] + (long)n0 * DDIM; op.ldb = DDIM;
    float acc[4][4][4] = {};
    run_gemm_1(op, 8, sb, acc);

    const int lane = threadIdx.x & 31, wid = threadIdx.x >> 5;
    const int wm = (wid >> 2) * 64, wn = (wid & 3) * 32;
    const int gr = lane >> 2, cp = (lane & 3) * 2;
#pragma unroll
    for (int mi = 0; mi < 4; mi++)
#pragma unroll
        for (int ni = 0; ni < 4; ni++)
#pragma unroll
            for (int h = 0; h < 2; h++) {
                int r = wm + mi * 16 + gr + h * 8;
                int c = wn + ni * 8 + cp;
                long base = (m0 + r) * (long)DDIM + n0 + c;
                float2 rv = *reinterpret_cast<const float2*>(q + base);
                *reinterpret_cast<float2*>(g_fc + base) =
                    make_float2(acc[mi][ni][h * 2] * WINV + rv.x,
                                acc[mi][ni][h * 2 + 1] * WINV + rv.y);
            }
}

// ---------------------------------------------------------------------------
// fp32 -> fp16 hi/lo splits
// ---------------------------------------------------------------------------
__global__ __launch_bounds__(256)
void split_qkv(const float* __restrict__ q, const float* __restrict__ k,
               const float* __restrict__ v) {
    const int y = blockIdx.y;
    long i = (long)blockIdx.x * 256 + threadIdx.x;
    const float* s = (y == 0) ? q : (y == 1) ? k : v;
    float4 vv = reinterpret_cast<const float4*>(s)[i];
    float hx, lx, hy, ly, hz, lz, hw, lw;
    split1h(vv.x, hx, lx); split1h(vv.y, hy, ly);
    split1h(vv.z, hz, lz); split1h(vv.w, hw, lw);
    uint2 hh = make_uint2(pack_h2(hx, hy), pack_h2(hz, hw));
    uint2 ll = make_uint2(pack_h2(lx, ly), pack_h2(lz, lw));
    if (y == 0)      { reinterpret_cast<uint2*>(g_qh)[i] = hh; reinterpret_cast<uint2*>(g_ql)[i] = ll; }
    else if (y == 1) { reinterpret_cast<uint2*>(g_kh)[i] = hh; reinterpret_cast<uint2*>(g_kl)[i] = ll; }
    else             { reinterpret_cast<uint2*>(g_vh)[i] = hh; }
}

__global__ __launch_bounds__(256)
void split_dist(const float* __restrict__ d) {
    long i = (long)blockIdx.x * 256 + threadIdx.x;
    float4 vv = reinterpret_cast<const float4*>(d)[i];
    float hx, lx, hy, ly, hz, lz, hw, lw;
    split1h(vv.x, hx, lx); split1h(vv.y, hy, ly);
    split1h(vv.z, hz, lz); split1h(vv.w, hw, lw);
    reinterpret_cast<uint2*>(g_disth)[i] = make_uint2(pack_h2(hx, hy), pack_h2(hz, hw));
    reinterpret_cast<uint2*>(g_distl)[i] = make_uint2(pack_h2(lx, ly), pack_h2(lz, lw));
}

__global__ __launch_bounds__(256)
void split_w(const float* __restrict__ w0, const float* __restrict__ w1,
             const float* __restrict__ w2, const float* __restrict__ w3,
             const float* __restrict__ w4, const float* __restrict__ w5) {
    const float* s; int wi = blockIdx.y;
    switch (wi) {
        case 0: s = w0; break; case 1: s = w1; break; case 2: s = w2; break;
        case 3: s = w3; break; case 4: s = w4; break; default: s = w5; break;
    }
    long i = (long)blockIdx.x * 256 + threadIdx.x;
    float4 vv = reinterpret_cast<const float4*>(s)[i];
    float hx, lx, hy, ly, hz, lz, hw, lw;
    split1h(vv.x * WSC, hx, lx); split1h(vv.y * WSC, hy, ly);
    split1h(vv.z * WSC, hz, lz); split1h(vv.w * WSC, hw, lw);
    reinterpret_cast<uint2*>(g_Wh[wi])[i] = make_uint2(pack_h2(hx, hy), pack_h2(hz, hw));
    reinterpret_cast<uint2*>(g_Wl[wi])[i] = make_uint2(pack_h2(lx, ly), pack_h2(lz, lw));
}

// ---------------------------------------------------------------------------
// LayerNorm over D=512
// ---------------------------------------------------------------------------
__global__ __launch_bounds__(128)
void ln_kernel(const float* __restrict__ gamma, const float* __restrict__ beta,
               float* __restrict__ out) {
    const long row = blockIdx.x;
    const int  t   = threadIdx.x;
    float4 v = reinterpret_cast<const float4*>(g_fc)[row * 128 + t];
    float s  = v.x + v.y + v.z + v.w;
    float s2 = v.x * v.x + v.y * v.y + v.z * v.z + v.w * v.w;
#pragma unroll
    for (int o = 16; o; o >>= 1) {
        s  += __shfl_xor_sync(0xffffffffu, s,  o);
        s2 += __shfl_xor_sync(0xffffffffu, s2, o);
    }
    __shared__ float ss[4], ss2[4];
    if ((t & 31) == 0) { ss[t >> 5] = s; ss2[t >> 5] = s2; }
    __syncthreads();
    s  = ss[0] + ss[1] + ss[2] + ss[3];
    s2 = ss2[0] + ss2[1] + ss2[2] + ss2[3];
    const float mu  = s * (1.0f / 512.0f);
    const float var = s2 * (1.0f / 512.0f) - mu * mu;
    const float inv = rsqrtf(var + 1e-6f);
    float4 g  = reinterpret_cast<const float4*>(gamma)[t];
    float4 be = reinterpret_cast<const float4*>(beta)[t];
    float4 o;
    o.x = (v.x - mu) * inv * g.x + be.x;
    o.y = (v.y - mu) * inv * g.y + be.y;
    o.z = (v.z - mu) * inv * g.z + be.z;
    o.w = (v.w - mu) * inv * g.w + be.w;
    reinterpret_cast<float4*>(out)[row * 128 + t] = o;
}

// ---------------------------------------------------------------------------
extern "C" void kernel_launch(void* const* d_in, const int* in_sizes, int n_in,
                              void* d_out, int out_size)
{
    (void)in_sizes; (void)n_in; (void)out_size;
    const float* q     = (const float*)d_in[0];
    const float* k     = (const float*)d_in[1];
    const float* v     = (const float*)d_in[2];
    const int*   lens  = (const int*)  d_in[3];
    const float* dist  = (const float*)d_in[4];
    const float* Wq    = (const float*)d_in[5];
    const float* Wk    = (const float*)d_in[6];
    const float* Wv    = (const float*)d_in[7];
    const float* Wqt   = (const float*)d_in[8];
    const float* Wkt   = (const float*)d_in[9];
    const float* Wfc   = (const float*)d_in[10];
    const float* gamma = (const float*)d_in[11];
    const float* beta  = (const float*)d_in[12];

    float* out_ln   = (float*)d_out;                       // [B, L, D]
    float* out_attn = out_ln + (size_t)BB * LSEQ * DDIM;   // [B, L, L]

    static cudaStream_t s1 = nullptr;
    static cudaEvent_t ev1 = nullptr, ev2 = nullptr;
    if (!s1) {
        cudaStreamCreateWithFlags(&s1, cudaStreamNonBlocking);
        cudaEventCreateWithFlags(&ev1, cudaEventDisableTiming);
        cudaEventCreateWithFlags(&ev2, cudaEventDisableTiming);
    }

    cudaFuncSetAttribute(proj1p_tc, cudaFuncAttributeMaxDynamicSharedMemorySize, SMEM_MIN);
    cudaFuncSetAttribute(proj3p_tc, cudaFuncAttributeMaxDynamicSharedMemorySize, SMEM_BIG);
    cudaFuncSetAttribute(bmm_tc,    cudaFuncAttributeMaxDynamicSharedMemorySize, SMEM_BIG);
    cudaFuncSetAttribute(attn_tc,   cudaFuncAttributeMaxDynamicSharedMemorySize, SMEM_BIG);
    cudaFuncSetAttribute(av_tc,     cudaFuncAttributeMaxDynamicSharedMemorySize, SMEM_MIN);
    cudaFuncSetAttribute(fc_tc,     cudaFuncAttributeMaxDynamicSharedMemorySize, SMEM_MIN);

    // main: input splits that everything downstream needs
    split_qkv <<<dim3(NQ / 4 / 256, 3), 256>>>(q, k, v);
    split_w   <<<dim3(NW / 4 / 256, 6), 256>>>(Wq, Wk, Wv, Wqt, Wkt, Wfc);

    // fork: independent work on s1 (proj1p + attn zero-fill)
    cudaEventRecord(ev1, 0);
    cudaStreamWaitEvent(s1, ev1, 0);
    proj1p_tc<<<dim3(4, 128, 3), 256, SMEM_MIN, s1>>>(lens);
    attn_zero<<<dim3(8, 8, 16), 256, 0, s1>>>(out_attn, lens);
    cudaEventRecord(ev2, s1);

    // main: critical chain
    split_dist<<<NATT / 4 / 256, 256>>>(dist);
    proj3p_tc<<<dim3(4, 128, 2), 256, SMEM_BIG>>>(lens);
    bmm_tc   <<<dim3(4, 8, 32),  256, SMEM_BIG>>>(lens);

    // join, then serial tail
    cudaStreamWaitEvent(0, ev2, 0);
    attn_tc<<<dim3(8, 8, 16),  256, SMEM_BIG>>>(out_attn, lens);
    av_tc  <<<dim3(4, 8, 16),  256, SMEM_MIN>>>(lens);
    fc_tc  <<<dim3(4, 128, 1), 256, SMEM_MIN>>>(q);
    ln_kernel<<<BB * LSEQ, 128>>>(gamma, beta, out_ln);
}

// round 15
// speedup vs baseline: 1.2514x; 1.0303x over previous
#include <cuda_runtime.h>
#include <cuda_fp16.h>
#include <stdint.h>
#include <math.h>

#define BB   16
#define LSEQ 1024
#define DDIM 512
typedef __half h16;

#define NQ   8388608    // B*L*D
#define NATT 16777216   // B*L*L
#define NW   262144     // D*D
#define WSC  32.0f
#define WINV 0.03125f

// ---------------- scratch (device globals; no allocation allowed) ----------
__device__ __align__(16) h16 g_qh[NQ],    g_ql[NQ];
__device__ __align__(16) h16 g_kh[NQ],    g_kl[NQ];
__device__ __align__(16) h16 g_vh[NQ];                     // v: hi only
__device__ __align__(16) h16 g_disth[NATT], g_distl[NATT];
__device__ __align__(16) h16 g_Wh[2][NW], g_Wl[2][NW];     // 32*W split: Wqt, Wkt
__device__ __align__(16) h16 g_Gt[NW];                     // 32 * (Wk^T Wq)^T  [d'][d]
__device__ __align__(16) h16 g_H [NW];                     // 32 * (Wfc Wv)    [i][d]
__device__ __align__(16) h16 g_qph[NQ];                    // qpf = q (Wq^T Wk), hi only
__device__ __align__(16) h16 g_vpTh[NQ];                   // vpfT [b][d][m], hi only
__device__ __align__(16) h16 g_qt0Th[NQ], g_qt0Tl[NQ];     // [b][d][m], B in bmm
__device__ __align__(16) h16 g_kt0Th[NQ], g_kt0Tl[NQ];
__device__ __align__(16) h16 g_qth[NQ],   g_qtl[NQ];       // A in attn op1 (3p)
__device__ __align__(16) h16 g_kth[NQ],   g_ktl[NQ];       // B in attn op1
__device__ __align__(16) h16 g_ath[NATT];                  // hi only (A in av)
__device__ float g_fc[NQ];

// ---------------- helpers ---------------------------------------------------
__device__ __forceinline__ uint32_t smem_u32(const void* p) {
    return (uint32_t)__cvta_generic_to_shared(p);
}
__device__ __forceinline__ uint32_t pack_h2(float a, float b) {
    __half2 t = __floats2half2_rn(a, b);
    return *reinterpret_cast<uint32_t*>(&t);
}
__device__ __forceinline__ void split1h(float v, float& h, float& l) {
    h = __half2float(__float2half_rn(v));
    l = v - h;
}
__device__ __forceinline__ float tanh_fast(float x) {
    float y;
    asm("tanh.approx.f32 %0, %1;" : "=f"(y) : "f"(x));
    return y;
}

#define BUF_SZ       65536
#define SMEM_BIG     (2 * BUF_SZ)
#define MBUF_SZ      32768
#define SMEM_MIN     (2 * MBUF_SZ)

__device__ __forceinline__ uint32_t swz(uint32_t base, int row, int cb) {
    uint32_t off = ((uint32_t)row << 7) + (uint32_t)cb;
    return base + (off ^ ((off >> 3) & 0x70));
}
__device__ __forceinline__ uint32_t a_addr(uint32_t base, int row0, int kb, int lane) {
    int mat = lane >> 3;
    return swz(base, row0 + (lane & 7) + ((mat & 1) << 3), kb + ((mat >> 1) << 4));
}
__device__ __forceinline__ uint32_t b_addr(uint32_t base, int n0, int kb, int lane) {
    int mat = lane >> 3;
    return swz(base, n0 + (lane & 7) + ((mat >> 1) << 3), kb + ((mat & 1) << 4));
}
__device__ __forceinline__ void ldsm4(uint32_t a, uint32_t* r) {
    asm volatile("ldmatrix.sync.aligned.m8n8.x4.shared.b16 {%0,%1,%2,%3}, [%4];"
                 : "=r"(r[0]), "=r"(r[1]), "=r"(r[2]), "=r"(r[3]) : "r"(a));
}
__device__ __forceinline__ void mma16816(float* d, const uint32_t* a, const uint32_t* b) {
    asm volatile(
        "mma.sync.aligned.m16n8k16.row.col.f32.f16.f16.f32 "
        "{%0,%1,%2,%3}, {%4,%5,%6,%7}, {%8,%9}, {%0,%1,%2,%3};"
        : "+f"(d[0]), "+f"(d[1]), "+f"(d[2]), "+f"(d[3])
        : "r"(a[0]), "r"(a[1]), "r"(a[2]), "r"(a[3]), "r"(b[0]), "r"(b[1]));
}

// mode: 1 = Ah*Bh; 3 = Ah*Bh + Ah*Bl + Al*Bh
struct GOps { const h16 *Ah, *Al, *Bh, *Bl; int lda, ldb, mode; };

__device__ __forceinline__ void load_tile_async(const h16* __restrict__ g, int ld,
                                                uint32_t sdst) {
    int t = threadIdx.x;
#pragma unroll
    for (int i = 0; i < 4; i++) {
        int u   = t + (i << 8);
        int row = u >> 3;
        int seg = (u & 7) << 4;
        const char* src = reinterpret_cast<const char*>(g + (long)row * ld) + seg;
        asm volatile("cp.async.cg.shared.global [%0], [%1], 16;"
                     :: "r"(swz(sdst, row, seg)), "l"(src));
    }
}

// ===== big (up-to-3p) path: proj3p / bmm / attn =====
__device__ __forceinline__ void issue_chunk(const GOps& o, int k0, uint32_t buf) {
    load_tile_async(o.Ah + k0, o.lda, buf);
    if (o.mode == 3) load_tile_async(o.Al + k0, o.lda, buf + 16384);
    load_tile_async(o.Bh + k0, o.ldb, buf + 32768);
    if (o.mode >= 2) load_tile_async(o.Bl + k0, o.ldb, buf + 49152);
    asm volatile("cp.async.commit_group;");
}
__device__ __forceinline__ void compute_chunk(uint32_t buf, int lane, int wm, int wn,
                                              float acc[4][4][4], int mode) {
#pragma unroll
    for (int ks = 0; ks < 4; ks++) {
        const int kb = ks * 32;
        uint32_t aH[4][4], aL[4][4], bH[8], bL[8];
#pragma unroll
        for (int mi = 0; mi < 4; mi++) ldsm4(a_addr(buf, wm + mi * 16, kb, lane), aH[mi]);
        if (mode == 3) {
#pragma unroll
            for (int mi = 0; mi < 4; mi++)
                ldsm4(a_addr(buf + 16384, wm + mi * 16, kb, lane), aL[mi]);
        }
        ldsm4(b_addr(buf + 32768, wn,      kb, lane), bH);
        ldsm4(b_addr(buf + 32768, wn + 16, kb, lane), bH + 4);
        if (mode >= 2) {
            ldsm4(b_addr(buf + 49152, wn,      kb, lane), bL);
            ldsm4(b_addr(buf + 49152, wn + 16, kb, lane), bL + 4);
        }
#pragma unroll
        for (int mi = 0; mi < 4; mi++)
#pragma unroll
            for (int ni = 0; ni < 4; ni++)
                mma16816(acc[mi][ni], aH[mi], bH + ni * 2);
        if (mode >= 2) {
#pragma unroll
            for (int mi = 0; mi < 4; mi++)
#pragma unroll
                for (int ni = 0; ni < 4; ni++)
                    mma16816(acc[mi][ni], aH[mi], bL + ni * 2);
        }
        if (mode == 3) {
#pragma unroll
            for (int mi = 0; mi < 4; mi++)
#pragma unroll
                for (int ni = 0; ni < 4; ni++)
                    mma16816(acc[mi][ni], aL[mi], bH + ni * 2);
        }
    }
}
__device__ __forceinline__ void run_gemm(const GOps* ops, int nops, int cpo,
                                         uint32_t sb, float acc[4][4][4]) {
    const int lane = threadIdx.x & 31, wid = threadIdx.x >> 5;
    const int wm = (wid >> 2) * 64, wn = (wid & 3) * 32;
    const int C = nops * cpo;

    issue_chunk(ops[0], 0, sb);
    for (int c = 0; c < C; c++) {
        if (c + 1 < C) {
            const GOps& o = ops[(c + 1) / cpo];
            issue_chunk(o, ((c + 1) % cpo) * 64, sb + ((c + 1) & 1) * BUF_SZ);
            asm volatile("cp.async.wait_group 1;" ::: "memory");
        } else {
            asm volatile("cp.async.wait_group 0;" ::: "memory");
        }
        __syncthreads();
        compute_chunk(sb + (c & 1) * BUF_SZ, lane, wm, wn, acc, ops[c / cpo].mode);
        __syncthreads();
    }
}

// ===== minimal (1p) path =====
__device__ __forceinline__ void issue_chunk_1(const GOps& o, int k0, uint32_t buf) {
    load_tile_async(o.Ah + k0, o.lda, buf);
    load_tile_async(o.Bh + k0, o.ldb, buf + 16384);
    asm volatile("cp.async.commit_group;");
}
__device__ __forceinline__ void compute_chunk_1(uint32_t buf, int lane, int wm, int wn,
                                                float acc[4][4][4]) {
#pragma unroll
    for (int ks = 0; ks < 4; ks++) {
        const int kb = ks * 32;
        uint32_t aH[4][4], bH[8];
#pragma unroll
        for (int mi = 0; mi < 4; mi++) ldsm4(a_addr(buf, wm + mi * 16, kb, lane), aH[mi]);
        ldsm4(b_addr(buf + 16384, wn,      kb, lane), bH);
        ldsm4(b_addr(buf + 16384, wn + 16, kb, lane), bH + 4);
#pragma unroll
        for (int mi = 0; mi < 4; mi++)
#pragma unroll
            for (int ni = 0; ni < 4; ni++)
                mma16816(acc[mi][ni], aH[mi], bH + ni * 2);
    }
}
__device__ __forceinline__ void run_gemm_1(const GOps& op, int cpo,
                                           uint32_t sb, float acc[4][4][4]) {
    const int lane = threadIdx.x & 31, wid = threadIdx.x >> 5;
    const int wm = (wid >> 2) * 64, wn = (wid & 3) * 32;

    issue_chunk_1(op, 0, sb);
    for (int c = 0; c < cpo; c++) {
        if (c + 1 < cpo) {
            issue_chunk_1(op, (c + 1) * 64, sb + ((c + 1) & 1) * MBUF_SZ);
            asm volatile("cp.async.wait_group 1;" ::: "memory");
        } else {
            asm volatile("cp.async.wait_group 0;" ::: "memory");
        }
        __syncthreads();
        compute_chunk_1(sb + (c & 1) * MBUF_SZ, lane, wm, wn, acc);
        __syncthreads();
    }
}

// epilogue helpers
__device__ __forceinline__ void epi_hl(h16* Dh, h16* Dl, long m0, int n0, int ld,
                                       const float acc[4][4][4], float sc) {
    const int lane = threadIdx.x & 31, wid = threadIdx.x >> 5;
    const int wm = (wid >> 2) * 64, wn = (wid & 3) * 32;
    const int gr = lane >> 2, cp = (lane & 3) * 2;
#pragma unroll
    for (int mi = 0; mi < 4; mi++)
#pragma unroll
        for (int ni = 0; ni < 4; ni++)
#pragma unroll
            for (int h = 0; h < 2; h++) {
                int r = wm + mi * 16 + gr + h * 8;
                int c = wn + ni * 8 + cp;
                float h0, l0, h1, l1;
                split1h(acc[mi][ni][h * 2]     * sc, h0, l0);
                split1h(acc[mi][ni][h * 2 + 1] * sc, h1, l1);
                long base = (m0 + r) * (long)ld + n0 + c;
                *reinterpret_cast<uint32_t*>(Dh + base) = pack_h2(h0, h1);
                *reinterpret_cast<uint32_t*>(Dl + base) = pack_h2(l0, l1);
            }
}
__device__ __forceinline__ void epi_h(h16* Dh, long m0, int n0, int ld,
                                      const float acc[4][4][4], float sc) {
    const int lane = threadIdx.x & 31, wid = threadIdx.x >> 5;
    const int wm = (wid >> 2) * 64, wn = (wid & 3) * 32;
    const int gr = lane >> 2, cp = (lane & 3) * 2;
#pragma unroll
    for (int mi = 0; mi < 4; mi++)
#pragma unroll
        for (int ni = 0; ni < 4; ni++)
#pragma unroll
            for (int h = 0; h < 2; h++) {
                int r = wm + mi * 16 + gr + h * 8;
                int c = wn + ni * 8 + cp;
                long base = (m0 + r) * (long)ld + n0 + c;
                *reinterpret_cast<uint32_t*>(Dh + base) =
                    pack_h2(acc[mi][ni][h * 2] * sc, acc[mi][ni][h * 2 + 1] * sc);
            }
}

// ---------------------------------------------------------------------------
// ww_gemm: z=0: Gt[d'][d] = 32 * sum_e Wk[e][d'] Wq[e][d]
//          z=1: H [i][d]  = 32 * sum_e Wfc[i][e] Wv[e][d]
// fp32 SIMT, 128x128 tile, grid (4,4,2). Only depends on raw W inputs.
// ---------------------------------------------------------------------------
__global__ __launch_bounds__(256)
void ww_gemm(const float* __restrict__ Wq, const float* __restrict__ Wk,
             const float* __restrict__ Wv, const float* __restrict__ Wfc) {
    __shared__ float As[16][128], Bs[16][128];
    const int z = blockIdx.z;
    const int m0 = blockIdx.y * 128, n0 = blockIdx.x * 128;
    const int t = threadIdx.x, ty = t >> 4, tx = t & 15;
    float acc[8][8] = {};

    for (int e0 = 0; e0 < 512; e0 += 16) {
#pragma unroll
        for (int i = 0; i < 8; i++) {
            int u = t + i * 256;
            int e = u >> 7, m = u & 127;
            As[e][m] = (z == 0) ? Wk[(long)(e0 + e) * 512 + m0 + m]
                                : Wfc[(long)(m0 + m) * 512 + e0 + e];
        }
        const float* B = (z == 0) ? Wq : Wv;
#pragma unroll
        for (int i = 0; i < 8; i++) {
            int u = t + i * 256;
            int e = u >> 7, n = u & 127;
            Bs[e][n] = B[(long)(e0 + e) * 512 + n0 + n];
        }
        __syncthreads();
#pragma unroll
        for (int e = 0; e < 16; e++) {
            float av[8], bv[8];
#pragma unroll
            for (int i = 0; i < 8; i++) av[i] = As[e][ty * 8 + i];
#pragma unroll
            for (int j = 0; j < 8; j++) bv[j] = Bs[e][tx * 8 + j];
#pragma unroll
            for (int i = 0; i < 8; i++)
#pragma unroll
                for (int j = 0; j < 8; j++)
                    acc[i][j] += av[i] * bv[j];
        }
        __syncthreads();
    }
    h16* D = (z == 0) ? g_Gt : g_H;
#pragma unroll
    for (int i = 0; i < 8; i++)
#pragma unroll
        for (int j = 0; j < 8; j++)
            D[(long)(m0 + ty * 8 + i) * 512 + n0 + tx * 8 + j] =
                __float2half_rn(acc[i][j] * WSC);
}

// ---------------------------------------------------------------------------
// proj1p: z=0 qpf = q*Gt^T; z=1 vpfT = (v*H^T)^T  (1-product, hi-only)
// ---------------------------------------------------------------------------
__global__ __launch_bounds__(256, 2)
void proj1p_tc(const int* __restrict__ lens) {
    extern __shared__ char smem[];
    uint32_t sb = smem_u32(smem);

    const int z = blockIdx.z;
    const long m0 = (long)blockIdx.y * 128;

    if (z == 1) {   // vpf rows beyond roundup(len,64) never contribute
        const int len = lens[(int)(m0 >> 10)];
        if ((int)(m0 & 1023) >= ((len + 63) & ~63)) return;
    }

    const int n0 = blockIdx.x * 128;
    GOps op;
    op.lda = DDIM; op.ldb = DDIM; op.Al = nullptr; op.Bl = nullptr; op.mode = 1;
    h16* Dh;
    if (z == 0) { op.Ah = g_qh; op.Bh = g_Gt; Dh = g_qph;  }
    else        { op.Ah = g_vh; op.Bh = g_H;  Dh = g_vpTh; }
    op.Ah += m0 * DDIM;
    op.Bh += (long)n0 * DDIM;

    float acc[4][4][4] = {};
    run_gemm_1(op, 8, sb, acc);

    if (z == 0) { epi_h(Dh, m0, n0, DDIM, acc, WINV); return; }

    // z == 1: transposed hi-only store via SMEM staging
    h16* Sh = reinterpret_cast<h16*>(smem);
    const int lane = threadIdx.x & 31, wid = threadIdx.x >> 5;
    const int wm = (wid >> 2) * 64, wn = (wid & 3) * 32;
    const int gr = lane >> 2, cp = (lane & 3) * 2;
    __syncthreads();
#pragma unroll
    for (int mi = 0; mi < 4; mi++)
#pragma unroll
        for (int ni = 0; ni < 4; ni++)
#pragma unroll
            for (int h = 0; h < 2; h++) {
                int r = wm + mi * 16 + gr + h * 8;
                int c = wn + ni * 8 + cp;
                Sh[(c    ) * 136 + r] = __float2half_rn(acc[mi][ni][h * 2]     * WINV);
                Sh[(c + 1) * 136 + r] = __float2half_rn(acc[mi][ni][h * 2 + 1] * WINV);
            }
    __syncthreads();
    const int t = threadIdx.x;
    const int d = t >> 1, half = t & 1;
    const int bb = (int)(m0 >> 10), lpos0 = (int)(m0 & 1023);
    long base = ((long)bb * DDIM + n0 + d) * LSEQ + lpos0 + half * 64;
    const uint4* sh = reinterpret_cast<const uint4*>(Sh + d * 136 + half * 64);
    uint4* dh = reinterpret_cast<uint4*>(Dh + base);
#pragma unroll
    for (int j = 0; j < 8; j++) dh[j] = sh[j];
}

// ---------------------------------------------------------------------------
// proj3p: z = 0 qt0T, 1 kt0T  (3-product precision chain)
// ---------------------------------------------------------------------------
__global__ __launch_bounds__(256, 1)
void proj3p_tc() {
    extern __shared__ char smem[];
    uint32_t sb = smem_u32(smem);

    const int z = blockIdx.z;
    const long m0 = (long)blockIdx.y * 128;
    const int  n0 = blockIdx.x * 128;

    GOps op;
    op.lda = DDIM; op.ldb = DDIM; op.mode = 3;
    h16 *Dh, *Dl;
    if (z == 0) { op.Ah = g_qh; op.Al = g_ql; op.Bh = g_Wh[0]; op.Bl = g_Wl[0];
                  Dh = g_qt0Th; Dl = g_qt0Tl; }
    else        { op.Ah = g_kh; op.Al = g_kl; op.Bh = g_Wh[1]; op.Bl = g_Wl[1];
                  Dh = g_kt0Th; Dl = g_kt0Tl; }
    op.Ah += m0 * DDIM; op.Al += m0 * DDIM;
    op.Bh += (long)n0 * DDIM; op.Bl += (long)n0 * DDIM;

    float acc[4][4][4] = {};
    run_gemm(&op, 1, 8, sb, acc);

    h16* Sh = reinterpret_cast<h16*>(smem);
    h16* Sl = reinterpret_cast<h16*>(smem + 34816);
    const int lane = threadIdx.x & 31, wid = threadIdx.x >> 5;
    const int wm = (wid >> 2) * 64, wn = (wid & 3) * 32;
    const int gr = lane >> 2, cp = (lane & 3) * 2;
    __syncthreads();
#pragma unroll
    for (int mi = 0; mi < 4; mi++)
#pragma unroll
        for (int ni = 0; ni < 4; ni++)
#pragma unroll
            for (int h = 0; h < 2; h++) {
                int r = wm + mi * 16 + gr + h * 8;
                int c = wn + ni * 8 + cp;
                float h0, l0, h1, l1;
                split1h(acc[mi][ni][h * 2]     * WINV, h0, l0);
                split1h(acc[mi][ni][h * 2 + 1] * WINV, h1, l1);
                Sh[(c    ) * 136 + r] = __float2half_rn(h0);
                Sh[(c + 1) * 136 + r] = __float2half_rn(h1);
                Sl[(c    ) * 136 + r] = __float2half_rn(l0);
                Sl[(c + 1) * 136 + r] = __float2half_rn(l1);
            }
    __syncthreads();
    const int t = threadIdx.x;
    const int d = t >> 1, half = t & 1;
    const int bb = (int)(m0 >> 10), lpos0 = (int)(m0 & 1023);
    long base = ((long)bb * DDIM + n0 + d) * LSEQ + lpos0 + half * 64;
    const uint4* sh = reinterpret_cast<const uint4*>(Sh + d * 136 + half * 64);
    const uint4* sl = reinterpret_cast<const uint4*>(Sl + d * 136 + half * 64);
    uint4* dh = reinterpret_cast<uint4*>(Dh + base);
    uint4* dl = reinterpret_cast<uint4*>(Dl + base);
#pragma unroll
    for (int j = 0; j < 8; j++) { dh[j] = sh[j]; dl[j] = sl[j]; }
}

// ---------------------------------------------------------------------------
// Stage B: qt/kt = dist @ qt0/kt0   (K = 1024, 3-product)
// ---------------------------------------------------------------------------
__global__ __launch_bounds__(256, 1)
void bmm_tc(const int* __restrict__ lens) {
    extern __shared__ char smem[];
    uint32_t sb = smem_u32(smem);

    const int z = blockIdx.z, b = z >> 1, isK = z & 1;
    const long m0 = (long)blockIdx.y * 128;
    if (isK) {
        const int len = lens[b];
        if ((int)m0 >= ((len + 127) & ~127)) return;
    }
    const h16* Bh = isK ? g_kt0Th : g_qt0Th;
    const h16* Bl = isK ? g_kt0Tl : g_qt0Tl;
    h16* Dh = isK ? g_kth : g_qth;
    h16* Dl = isK ? g_ktl : g_qtl;

    const int n0 = blockIdx.x * 128;

    GOps op;
    op.Ah = g_disth + (long)b * LSEQ * LSEQ + m0 * LSEQ;
    op.Al = g_distl + (long)b * LSEQ * LSEQ + m0 * LSEQ;
    op.lda = LSEQ; op.mode = 3;
    op.Bh = Bh + (long)b * LSEQ * DDIM + (long)n0 * LSEQ;
    op.Bl = Bl + (long)b * LSEQ * DDIM + (long)n0 * LSEQ;
    op.ldb = LSEQ;
    float acc[4][4][4] = {};
    run_gemm(&op, 1, 16, sb, acc);

    epi_hl(Dh + (long)b * LSEQ * DDIM, Dl + (long)b * LSEQ * DDIM, m0, n0, DDIM, acc, 1.0f);
}

// ---------------------------------------------------------------------------
// attn zero-fill for fully-masked tiles
// ---------------------------------------------------------------------------
__global__ __launch_bounds__(256)
void attn_zero(float* __restrict__ out_attn, const int* __restrict__ lens) {
    const int b = blockIdx.z;
    const long m0 = (long)blockIdx.y * 128;
    const int  n0 = blockIdx.x * 128;
    if (n0 < lens[b]) return;
    const long arow0 = (long)b * LSEQ * LSEQ;
    const int t = threadIdx.x;
    const int r = t >> 1, half = t & 1;
    float4* dst = reinterpret_cast<float4*>(
        out_attn + arow0 + (m0 + r) * (long)LSEQ + n0 + half * 64);
    const float4 z4 = make_float4(0.f, 0.f, 0.f, 0.f);
#pragma unroll
    for (int j = 0; j < 16; j++) dst[j] = z4;
}

// ---------------------------------------------------------------------------
// Stage C: attn. op0: qpf * k^T (1p); op1: qt * kt^T (3p)
// ---------------------------------------------------------------------------
__global__ __launch_bounds__(256, 1)
void attn_tc(float* __restrict__ out_attn, const int* __restrict__ lens) {
    extern __shared__ char smem[];
    uint32_t sb = smem_u32(smem);

    const int b = blockIdx.z;
    const long m0 = (long)blockIdx.y * 128;
    const int  n0 = blockIdx.x * 128;
    const int  len = lens[b];
    if (n0 >= len) return;   // zero-filled by attn_zero
    const long arow0 = (long)b * LSEQ * LSEQ;

    const long po = (long)b * LSEQ * DDIM;
    GOps ops[2];
    ops[0].Ah = g_qph + po + m0 * DDIM; ops[0].Al = nullptr; ops[0].mode = 1;
    ops[0].Bh = g_kh + po + (long)n0 * DDIM; ops[0].Bl = nullptr;
    ops[0].lda = DDIM; ops[0].ldb = DDIM;
    ops[1].Ah = g_qth + po + m0 * DDIM; ops[1].Al = g_qtl + po + m0 * DDIM; ops[1].mode = 3;
    ops[1].Bh = g_kth + po + (long)n0 * DDIM; ops[1].Bl = g_ktl + po + (long)n0 * DDIM;
    ops[1].lda = DDIM; ops[1].ldb = DDIM;
    float acc[4][4][4] = {};
    run_gemm(ops, 2, 8, sb, acc);

    const float alpha = 0.044194173824159216f;   // 1/sqrt(512)
    const int lane = threadIdx.x & 31, wid = threadIdx.x >> 5;
    const int wm = (wid >> 2) * 64, wn = (wid & 3) * 32;
    const int gr = lane >> 2, cp = (lane & 3) * 2;

#pragma unroll
    for (int mi = 0; mi < 4; mi++)
#pragma unroll
        for (int ni = 0; ni < 4; ni++)
#pragma unroll
            for (int h = 0; h < 2; h++) {
                int r = wm + mi * 16 + gr + h * 8;
                int c = wn + ni * 8 + cp;
                int col = n0 + c;
                float t0 = (col     < len) ? tanh_fast(acc[mi][ni][h * 2]     * alpha) : 0.0f;
                float t1 = (col + 1 < len) ? tanh_fast(acc[mi][ni][h * 2 + 1] * alpha) : 0.0f;
                long base = arow0 + (m0 + r) * (long)LSEQ + col;
                *reinterpret_cast<float2*>(out_attn + base) = make_float2(t0, t1);
                *reinterpret_cast<uint32_t*>(g_ath + base) = pack_h2(t0, t1);
            }
}

// ---------------------------------------------------------------------------
// Stage D: fc = attn @ vpf + residual(q)  -> g_fc (fp32)
// (vpf = v*(Wfc*Wv)^T, so attn@vpf == out0@Wfc^T; fc stage is fused away)
// ---------------------------------------------------------------------------
__global__ __launch_bounds__(256, 2)
void av_tc(const int* __restrict__ lens, const float* __restrict__ q) {
    extern __shared__ char smem[];
    uint32_t sb = smem_u32(smem);

    const int b = blockIdx.z;
    const long m0 = (long)blockIdx.y * 128;
    const int  n0 = blockIdx.x * 128;
    const int  len = lens[b];
    const int  cpo = (len + 63) >> 6;

    GOps op;
    op.Ah = g_ath + (long)b * LSEQ * LSEQ + m0 * LSEQ;
    op.Al = nullptr; op.Bl = nullptr; op.mode = 1;
    op.lda = LSEQ;
    op.Bh = g_vpTh + (long)b * LSEQ * DDIM + (long)n0 * LSEQ;
    op.ldb = LSEQ;
    float acc[4][4][4] = {};
    run_gemm_1(op, cpo, sb, acc);

    const int lane = threadIdx.x & 31, wid = threadIdx.x >> 5;
    const int wm = (wid >> 2) * 64, wn = (wid & 3) * 32;
    const int gr = lane >> 2, cp = (lane & 3) * 2;
    const long grow0 = (long)b * LSEQ + m0;
#pragma unroll
    for (int mi = 0; mi < 4; mi++)
#pragma unroll
        for (int ni = 0; ni < 4; ni++)
#pragma unroll
            for (int h = 0; h < 2; h++) {
                int r = wm + mi * 16 + gr + h * 8;
                int c = wn + ni * 8 + cp;
                long base = (grow0 + r) * (long)DDIM + n0 + c;
                float2 rv = *reinterpret_cast<const float2*>(q + base);
                *reinterpret_cast<float2*>(g_fc + base) =
                    make_float2(acc[mi][ni][h * 2] + rv.x, acc[mi][ni][h * 2 + 1] + rv.y);
            }
}

// ---------------------------------------------------------------------------
// fp32 -> fp16 hi/lo splits
// ---------------------------------------------------------------------------
__global__ __launch_bounds__(256)
void split_qkv(const float* __restrict__ q, const float* __restrict__ k,
               const float* __restrict__ v) {
    const int y = blockIdx.y;
    long i = (long)blockIdx.x * 256 + threadIdx.x;
    const float* s = (y == 0) ? q : (y == 1) ? k : v;
    float4 vv = reinterpret_cast<const float4*>(s)[i];
    float hx, lx, hy, ly, hz, lz, hw, lw;
    split1h(vv.x, hx, lx); split1h(vv.y, hy, ly);
    split1h(vv.z, hz, lz); split1h(vv.w, hw, lw);
    uint2 hh = make_uint2(pack_h2(hx, hy), pack_h2(hz, hw));
    uint2 ll = make_uint2(pack_h2(lx, ly), pack_h2(lz, lw));
    if (y == 0)      { reinterpret_cast<uint2*>(g_qh)[i] = hh; reinterpret_cast<uint2*>(g_ql)[i] = ll; }
    else if (y == 1) { reinterpret_cast<uint2*>(g_kh)[i] = hh; reinterpret_cast<uint2*>(g_kl)[i] = ll; }
    else             { reinterpret_cast<uint2*>(g_vh)[i] = hh; }
}

__global__ __launch_bounds__(256)
void split_dist(const float* __restrict__ d) {
    long i = (long)blockIdx.x * 256 + threadIdx.x;
    float4 vv = reinterpret_cast<const float4*>(d)[i];
    float hx, lx, hy, ly, hz, lz, hw, lw;
    split1h(vv.x, hx, lx); split1h(vv.y, hy, ly);
    split1h(vv.z, hz, lz); split1h(vv.w, hw, lw);
    reinterpret_cast<uint2*>(g_disth)[i] = make_uint2(pack_h2(hx, hy), pack_h2(hz, hw));
    reinterpret_cast<uint2*>(g_distl)[i] = make_uint2(pack_h2(lx, ly), pack_h2(lz, lw));
}

__global__ __launch_bounds__(256)
void split_w(const float* __restrict__ w0, const float* __restrict__ w1) {
    const float* s = blockIdx.y ? w1 : w0;
    int wi = blockIdx.y;
    long i = (long)blockIdx.x * 256 + threadIdx.x;
    float4 vv = reinterpret_cast<const float4*>(s)[i];
    float hx, lx, hy, ly, hz, lz, hw, lw;
    split1h(vv.x * WSC, hx, lx); split1h(vv.y * WSC, hy, ly);
    split1h(vv.z * WSC, hz, lz); split1h(vv.w * WSC, hw, lw);
    reinterpret_cast<uint2*>(g_Wh[wi])[i] = make_uint2(pack_h2(hx, hy), pack_h2(hz, hw));
    reinterpret_cast<uint2*>(g_Wl[wi])[i] = make_uint2(pack_h2(lx, ly), pack_h2(lz, lw));
}

// ---------------------------------------------------------------------------
// LayerNorm over D=512
// ---------------------------------------------------------------------------
__global__ __launch_bounds__(128)
void ln_kernel(const float* __restrict__ gamma, const float* __restrict__ beta,
               float* __restrict__ out) {
    const long row = blockIdx.x;
    const int  t   = threadIdx.x;
    float4 v = reinterpret_cast<const float4*>(g_fc)[row * 128 + t];
    float s  = v.x + v.y + v.z + v.w;
    float s2 = v.x * v.x + v.y * v.y + v.z * v.z + v.w * v.w;
#pragma unroll
    for (int o = 16; o; o >>= 1) {
        s  += __shfl_xor_sync(0xffffffffu, s,  o);
        s2 += __shfl_xor_sync(0xffffffffu, s2, o);
    }
    __shared__ float ss[4], ss2[4];
    if ((t & 31) == 0) { ss[t >> 5] = s; ss2[t >> 5] = s2; }
    __syncthreads();
    s  = ss[0] + ss[1] + ss[2] + ss[3];
    s2 = ss2[0] + ss2[1] + ss2[2] + ss2[3];
    const float mu  = s * (1.0f / 512.0f);
    const float var = s2 * (1.0f / 512.0f) - mu * mu;
    const float inv = rsqrtf(var + 1e-6f);
    float4 g  = reinterpret_cast<const float4*>(gamma)[t];
    float4 be = reinterpret_cast<const float4*>(beta)[t];
    float4 o;
    o.x = (v.x - mu) * inv * g.x + be.x;
    o.y = (v.y - mu) * inv * g.y + be.y;
    o.z = (v.z - mu) * inv * g.z + be.z;
    o.w = (v.w - mu) * inv * g.w + be.w;
    reinterpret_cast<float4*>(out)[row * 128 + t] = o;
}

// ---------------------------------------------------------------------------
extern "C" void kernel_launch(void* const* d_in, const int* in_sizes, int n_in,
                              void* d_out, int out_size)
{
    (void)in_sizes; (void)n_in; (void)out_size;
    const float* q     = (const float*)d_in[0];
    const float* k     = (const float*)d_in[1];
    const float* v     = (const float*)d_in[2];
    const int*   lens  = (const int*)  d_in[3];
    const float* dist  = (const float*)d_in[4];
    const float* Wq    = (const float*)d_in[5];
    const float* Wk    = (const float*)d_in[6];
    const float* Wv    = (const float*)d_in[7];
    const float* Wqt   = (const float*)d_in[8];
    const float* Wkt   = (const float*)d_in[9];
    const float* Wfc   = (const float*)d_in[10];
    const float* gamma = (const float*)d_in[11];
    const float* beta  = (const float*)d_in[12];

    float* out_ln   = (float*)d_out;                       // [B, L, D]
    float* out_attn = out_ln + (size_t)BB * LSEQ * DDIM;   // [B, L, L]

    static cudaStream_t s1 = nullptr;
    static cudaEvent_t ev0 = nullptr, ev1 = nullptr, ev2 = nullptr;
    if (!s1) {
        cudaStreamCreateWithFlags(&s1, cudaStreamNonBlocking);
        cudaEventCreateWithFlags(&ev0, cudaEventDisableTiming);
        cudaEventCreateWithFlags(&ev1, cudaEventDisableTiming);
        cudaEventCreateWithFlags(&ev2, cudaEventDisableTiming);
    }

    cudaFuncSetAttribute(proj1p_tc, cudaFuncAttributeMaxDynamicSharedMemorySize, SMEM_MIN);
    cudaFuncSetAttribute(proj3p_tc, cudaFuncAttributeMaxDynamicSharedMemorySize, SMEM_BIG);
    cudaFuncSetAttribute(bmm_tc,    cudaFuncAttributeMaxDynamicSharedMemorySize, SMEM_BIG);
    cudaFuncSetAttribute(attn_tc,   cudaFuncAttributeMaxDynamicSharedMemorySize, SMEM_BIG);
    cudaFuncSetAttribute(av_tc,     cudaFuncAttributeMaxDynamicSharedMemorySize, SMEM_MIN);

    // fork s1 immediately: ww_gemm depends only on W inputs; overlaps main's splits
    cudaEventRecord(ev0, 0);
    cudaStreamWaitEvent(s1, ev0, 0);
    ww_gemm<<<dim3(4, 4, 2), 256, 0, s1>>>(Wq, Wk, Wv, Wfc);
    attn_zero<<<dim3(8, 8, 16), 256, 0, s1>>>(out_attn, lens);

    // main: input splits
    split_qkv <<<dim3(NQ / 4 / 256, 3), 256>>>(q, k, v);
    split_w   <<<dim3(NW / 4 / 256, 2), 256>>>(Wqt, Wkt);
    cudaEventRecord(ev1, 0);
    cudaStreamWaitEvent(s1, ev1, 0);

    // s1: folded 1p projections (need splits + ww_gemm)
    proj1p_tc<<<dim3(4, 128, 2), 256, SMEM_MIN, s1>>>(lens);
    cudaEventRecord(ev2, s1);

    // main: critical chain
    split_dist<<<NATT / 4 / 256, 256>>>(dist);
    proj3p_tc<<<dim3(4, 128, 2), 256, SMEM_BIG>>>();
    bmm_tc   <<<dim3(4, 8, 32),  256, SMEM_BIG>>>(lens);

    // join, then serial tail
    cudaStreamWaitEvent(0, ev2, 0);
    attn_tc<<<dim3(8, 8, 16), 256, SMEM_BIG>>>(out_attn, lens);
    av_tc  <<<dim3(4, 8, 16), 256, SMEM_MIN>>>(lens, q);
    ln_kernel<<<BB * LSEQ, 128>>>(gamma, beta, out_ln);
}